// round 10
// baseline (speedup 1.0000x reference)
#include <cuda_runtime.h>
#include <cuda_fp16.h>
#include <cstdint>
#include <math.h>

#define NB    32
#define SQ    32
#define HH    1024
#define NHEAD 16
#define HS    64
#define NLAY  4
#define THIST 8
#define TACT  8
#define HIN   512
#define AIN   64
#define RS    (NB*HH)          // 32768: row stride between s-positions

#define TOK_ELEMS (NB*SQ*HH)   // 1048576
#define WMAT      (HH*HH)      // 1048576

// token row layout: row = s*NB + b  (valid rows are prefix [0, 32*L))

// ---------------- scratch (device globals; no allocation) ----------------
__device__ float g_pe[SQ*HH];
__device__ float g_tokens[TOK_ELEMS];
__device__ float g_h[TOK_ELEMS];
__device__ float g_qbuf[NLAY*TOK_ELEMS];   // per-layer Q
__device__ float g_kbig[NLAY*TOK_ELEMS];   // per-layer K
__device__ float g_vbuf[TOK_ELEMS];
__device__ float g_tmp[TOK_ELEMS];
__device__ float g_spart[32*NB*HIN];
__device__ float g_srelu[NB*HIN];
__device__ __half g_hh[TOK_ELEMS];                 // fp16 activations
__device__ __half g_ctxh[TOK_ELEMS];
__device__ __half g_phh[NLAY*TOK_ELEMS];
__device__ __half g_WhT[20*WMAT];                  // fp16 weight hi [N,K]
__device__ __half g_WlT[20*WMAT];                  // fp16 weight lo [N,K]

// ---------------- helpers ----------------
__device__ __forceinline__ uint32_t s2u(const void* p) {
    uint32_t a;
    asm("{ .reg .u64 t; cvta.to.shared.u64 t, %1; cvt.u32.u64 %0, t; }" : "=r"(a) : "l"(p));
    return a;
}

#define LDM4(r, addr) \
    asm volatile("ldmatrix.sync.aligned.m8n8.x4.shared.b16 {%0,%1,%2,%3}, [%4];" \
        : "=r"((r)[0]), "=r"((r)[1]), "=r"((r)[2]), "=r"((r)[3]) : "r"(addr))

#define MMA_F16(d, a, b0v, b1v) \
    asm volatile("mma.sync.aligned.m16n8k16.row.col.f32.f16.f16.f32 " \
        "{%0,%1,%2,%3}, {%4,%5,%6,%7}, {%8,%9}, {%0,%1,%2,%3};" \
        : "+f"((d)[0]), "+f"((d)[1]), "+f"((d)[2]), "+f"((d)[3]) \
        : "r"((a)[0]), "r"((a)[1]), "r"((a)[2]), "r"((a)[3]), "r"(b0v), "r"(b1v))

#define CP_ASYNC16(sa, gp) \
    asm volatile("cp.async.cg.shared.global [%0], [%1], 16;" :: "r"(sa), "l"(gp))
#define CP_ASYNC16Z(sa, gp, sz) \
    asm volatile("cp.async.cg.shared.global [%0], [%1], 16, %2;" :: "r"(sa), "l"(gp), "r"(sz))
#define CP_COMMIT()  asm volatile("cp.async.commit_group;" ::: "memory")
#define CP_WAIT0()   asm volatile("cp.async.wait_group 0;" ::: "memory")
#define CP_WAIT1()   asm volatile("cp.async.wait_group 1;" ::: "memory")
#define CP_WAIT2()   asm volatile("cp.async.wait_group 2;" ::: "memory")

// ---------------- weight transpose + fp16 split: W[K,N] -> WT[N,K] hi/lo ----------------
__global__ void wconv_kernel(const float* __restrict__ Wq, const float* __restrict__ Wk,
                             const float* __restrict__ Wv, const float* __restrict__ Wo,
                             const float* __restrict__ Wfc,
                             __half* __restrict__ WhT, __half* __restrict__ WlT)
{
    int z = blockIdx.z;                 // 0..19 = type*4 + layer
    int type = z >> 2, layer = z & 3;
    const float* bases[5] = {Wq, Wk, Wv, Wo, Wfc};
    const float* W = bases[type] + (size_t)layer * WMAT;
    __shared__ float t[32][33];
    int x0 = blockIdx.x * 32;  // K
    int y0 = blockIdx.y * 32;  // N
    int tr = threadIdx.x >> 5, tc = threadIdx.x & 31;
    #pragma unroll
    for (int u = 0; u < 4; u++) {
        int r = tr + u * 8;
        t[r][tc] = W[(size_t)(x0 + r) * HH + y0 + tc];
    }
    __syncthreads();
    size_t ob = (size_t)z * WMAT;
    #pragma unroll
    for (int u = 0; u < 4; u++) {
        int r = tr + u * 8;
        float v = t[tc][r];
        __half hi = __float2half(v);
        __half lo = __float2half(v - __half2float(hi));
        size_t off = ob + (size_t)(y0 + r) * HH + x0 + tc;
        WhT[off] = hi;
        WlT[off] = lo;
    }
}

// ---------------- fp16 2-term tensor-core GEMM (mma.sync) ----------------
// C[M,1024] = A x (Wh + Wl)^T.  A fp16 [M,K]; W stored [N,K] hi/lo.
// CTA tile 128(M) x 128(N), 256 threads, 1 CTA/SM.
// K-chunk 64, 4-buffer/3-outstanding cp.async pipeline.
// Stage (49152 B): A[0,16K) Bh[16K,32K) Bl[32K,48K)
#define STAGE 49152
#define NBUF  4
#define GEMM_SMEM (NBUF*STAGE)    // 196608

__device__ __forceinline__ void issue_stage(uint32_t sbase, int buf,
    const __half* __restrict__ A,
    const __half* __restrict__ Bh, const __half* __restrict__ Bl,
    int bm, int bn, int k0, int tid, int mvalid)
{
    uint32_t st = sbase + buf * STAGE;
    #pragma unroll
    for (int u = 0; u < 12; u++) {
        int id = tid + u * 256;             // 0..3071
        if (id < 1024) {
            int r = id >> 3, c = id & 7;
            const __half* gp = A + (size_t)(bm + r) * HH + k0 + c * 8;
            uint32_t sa = st + r * 128 + ((c ^ (r & 7)) << 4);
            uint32_t sz = ((bm + r) < mvalid) ? 16u : 0u;
            CP_ASYNC16Z(sa, gp, sz);
        } else {
            int sec = (id - 1024) >> 10;    // 0=Bh 1=Bl
            int t = (id - 1024) & 1023;
            int r = t >> 3, c = t & 7;
            const __half* gp = (sec ? Bl : Bh) + (size_t)(bn + r) * HH + k0 + c * 8;
            uint32_t sa = st + 16384 + sec * 16384 + r * 128 + ((c ^ (r & 7)) << 4);
            CP_ASYNC16(sa, gp);
        }
    }
    CP_COMMIT();
}

__device__ __forceinline__ void gemm_body(
    const __half* __restrict__ A,
    const __half* __restrict__ Bh, const __half* __restrict__ Bl,
    float* __restrict__ C, int mvalid)
{
    extern __shared__ char smem[];
    uint32_t sbase = s2u(smem);
    int tid = threadIdx.x, wid = tid >> 5, lane = tid & 31;
    int bm = blockIdx.y << 7, bn = blockIdx.x << 7;
    int warpM = (wid >> 2) << 6;   // 0 / 64
    int warpN = (wid & 3) << 5;    // 0..96

    issue_stage(sbase, 0, A, Bh, Bl, bm, bn, 0,   tid, mvalid);
    issue_stage(sbase, 1, A, Bh, Bl, bm, bn, 64,  tid, mvalid);
    issue_stage(sbase, 2, A, Bh, Bl, bm, bn, 128, tid, mvalid);

    float acc[4][4][4] = {};

    for (int s = 0; s < 16; s++) {
        if (s < 14)       { CP_WAIT2(); }
        else if (s == 14) { CP_WAIT1(); }
        else              { CP_WAIT0(); }
        __syncthreads();
        if (s + 3 < 16)
            issue_stage(sbase, (s + 3) & 3, A, Bh, Bl, bm, bn, (s + 3) << 6, tid, mvalid);
        uint32_t st = sbase + (s & 3) * STAGE;
        #pragma unroll
        for (int kk = 0; kk < 4; kk++) {
            uint32_t ah[4][4];
            #pragma unroll
            for (int mt = 0; mt < 4; mt++) {
                int r = warpM + mt * 16 + (lane & 15);
                int ch = kk * 2 + (lane >> 4);
                uint32_t ad = st + r * 128 + ((ch ^ (r & 7)) << 4);
                LDM4(ah[mt], ad);
            }
            uint32_t bh[2][4], bl[2][4];
            #pragma unroll
            for (int nt = 0; nt < 2; nt++) {
                int r = warpN + nt * 16 + (lane & 7) + ((lane >> 4) << 3);
                int ch = kk * 2 + ((lane >> 3) & 1);
                uint32_t bd = st + 16384 + r * 128 + ((ch ^ (r & 7)) << 4);
                LDM4(bh[nt], bd);
                LDM4(bl[nt], bd + 16384);
            }
            #pragma unroll
            for (int mt = 0; mt < 4; mt++) {
                #pragma unroll
                for (int j = 0; j < 4; j++) {
                    uint32_t b0 = bh[j >> 1][(j & 1) * 2], b1 = bh[j >> 1][(j & 1) * 2 + 1];
                    uint32_t c0 = bl[j >> 1][(j & 1) * 2], c1 = bl[j >> 1][(j & 1) * 2 + 1];
                    MMA_F16(acc[mt][j], ah[mt], b0, b1);
                    MMA_F16(acc[mt][j], ah[mt], c0, c1);
                }
            }
        }
    }

    #pragma unroll
    for (int mt = 0; mt < 4; mt++) {
        int row = bm + warpM + mt * 16 + (lane >> 2);
        #pragma unroll
        for (int j = 0; j < 4; j++) {
            int col = bn + warpN + j * 8 + ((lane & 3) << 1);
            *(float2*)&C[(size_t)row * HH + col] =
                make_float2(acc[mt][j][0], acc[mt][j][1]);
            *(float2*)&C[(size_t)(row + 8) * HH + col] =
                make_float2(acc[mt][j][2], acc[mt][j][3]);
        }
    }
}

__global__ void __launch_bounds__(256, 1) gemm_tc(
    const __half* __restrict__ A,
    const __half* __restrict__ Bh, const __half* __restrict__ Bl,
    float* __restrict__ C, int mvalid)
{
    gemm_body(A, Bh, Bl, C, mvalid);
}

// step-0 QKV: all operands from current hh
__global__ void __launch_bounds__(256, 1) gemm_qkv3(
    const __half* __restrict__ hh,
    const __half* __restrict__ WhT, const __half* __restrict__ WlT,
    size_t sq, size_t sk, size_t sv,
    float* __restrict__ Q, float* __restrict__ K, float* __restrict__ V, int mvalid)
{
    int z = blockIdx.z;
    size_t off = (z == 0) ? sq : (z == 1) ? sk : sv;
    float* C = (z == 0) ? Q : (z == 1) ? K : V;
    gemm_body(hh, WhT + off, WlT + off, C, mvalid);
}

// look-ahead Q,K for next step from prev_h[j]
__global__ void __launch_bounds__(256, 1) gemm_qk(
    const __half* __restrict__ ph,
    const __half* __restrict__ WhT, const __half* __restrict__ WlT,
    size_t sq, size_t sk,
    float* __restrict__ Q, float* __restrict__ K, int mvalid)
{
    int z = blockIdx.z;
    size_t off = (z == 0) ? sq : sk;
    float* C = (z == 0) ? Q : K;
    gemm_body(ph, WhT + off, WlT + off, C, mvalid);
}

// ---------------- positional encoding ----------------
__global__ void pe_kernel(float* __restrict__ pe)
{
    int s = blockIdx.x;
    for (int h = threadIdx.x; h < HH; h += 256) {
        float e = (float)(2 * (h / 2)) * (1.0f / HH);
        float freq = exp2f(-e * 13.287712379549449f);   // log2(10000)
        float angle = (float)s * freq;
        pe[s*HH + h] = (h & 1) ? cosf(angle) : sinf(angle);
    }
}

__global__ void zero4_kernel(float* __restrict__ p)
{
    int idx = blockIdx.x*256 + threadIdx.x;
    ((float4*)p)[idx] = make_float4(0.f,0.f,0.f,0.f);
}

// ---------------- small row GEMM + relu into tokens ([s][b] layout) ----------------
__global__ void vecmat_relu(const float* __restrict__ X, int xstride,
                            const float* __restrict__ W, int K,
                            int mode, int off, float* __restrict__ tokens)
{
    int r = blockIdx.x;
    __shared__ float xs[512];
    for (int k = threadIdx.x; k < K; k += 256) xs[k] = X[r*xstride + k];
    __syncthreads();
    int drow;
    if      (mode == 1) drow = (2*(r&7))*NB + (r>>3);
    else if (mode == 2) drow = (2*(r&7)+1)*NB + (r>>3);
    else                drow = off*NB + r;
    int c = blockIdx.y*256 + threadIdx.x;
    float acc = 0.f;
    for (int k = 0; k < K; k++) acc = fmaf(xs[k], W[k*HH + c], acc);
    tokens[drow*HH + c] = fmaxf(acc, 0.f);
}

// ---------------- h = tokens + pe (valid rows), fused fp16 convert ----------------
__global__ void addpe_kernel(const float* __restrict__ tokens,
                             const float* __restrict__ pe,
                             float* __restrict__ h,
                             __half* __restrict__ hh, int L)
{
    int i = blockIdx.x*256 + threadIdx.x;
    float v = tokens[i];
    int srow = i >> 15;                       // s index ([s][b] layout)
    if (srow < L) v += pe[srow*HH + (i & 1023)];
    h[i] = v;
    hh[i] = __float2half(v);
}

// ---------------- attention (one block per (b, head)), [s][b] layout ----------------
__global__ void attn_kernel(int L, const float* __restrict__ Q,
                            const float* __restrict__ K,
                            const float* __restrict__ V,
                            __half* __restrict__ ctxh)
{
    __shared__ float Qs[32][64];
    __shared__ float KsT[64][33];
    __shared__ float Vs[32][64];
    __shared__ float P[32][33];
    int tid = threadIdx.x;
    int b = blockIdx.x >> 4, hd = blockIdx.x & 15;
    const float* qb = Q + b*HH + hd*HS;
    const float* kb = K + b*HH + hd*HS;
    const float* vb = V + b*HH + hd*HS;
    #pragma unroll
    for (int t = 0; t < 2; t++) {
        int f = tid + t*256;
        int row = f >> 4, c4 = (f & 15) << 2;
        float4 q4 = *(const float4*)(qb + row*RS + c4);
        *(float4*)&Qs[row][c4] = q4;
        float4 k4 = *(const float4*)(kb + row*RS + c4);
        KsT[c4+0][row] = k4.x; KsT[c4+1][row] = k4.y;
        KsT[c4+2][row] = k4.z; KsT[c4+3][row] = k4.w;
        float4 v4 = *(const float4*)(vb + row*RS + c4);
        *(float4*)&Vs[row][c4] = v4;
    }
    __syncthreads();
    #pragma unroll
    for (int t = 0; t < 4; t++) {
        int p = tid + t*256;
        int qr = p >> 5, kr = p & 31;
        float sc = 0.f;
        #pragma unroll
        for (int d = 0; d < 64; d++) sc = fmaf(Qs[qr][d], KsT[d][kr], sc);
        P[qr][kr] = sc * 0.125f;
    }
    __syncthreads();
    int w = tid >> 5, lane = tid & 31;
    #pragma unroll
    for (int r = 0; r < 4; r++) {
        int qr = w + r*8;
        bool vq = qr < L, vk = lane < L;
        float v = (vq && vk) ? P[qr][lane] : -1e30f;
        float mx = v;
        #pragma unroll
        for (int off = 16; off > 0; off >>= 1)
            mx = fmaxf(mx, __shfl_xor_sync(0xFFFFFFFFu, mx, off));
        float e = (vq && vk) ? expf(v - mx) : 0.f;
        float sm = e;
        #pragma unroll
        for (int off = 16; off > 0; off >>= 1)
            sm += __shfl_xor_sync(0xFFFFFFFFu, sm, off);
        P[qr][lane] = vq ? (e / sm) : 0.f;
    }
    __syncthreads();
    __half* ch = ctxh + b*HH + hd*HS;
    #pragma unroll
    for (int t = 0; t < 8; t++) {
        int e = tid + t*256;
        int qr = e >> 6, d = e & 63;
        float acc = 0.f;
        #pragma unroll
        for (int k = 0; k < 32; k++) acc = fmaf(P[qr][k], Vs[k][d], acc);
        ch[qr*RS + d] = __float2half(acc);
    }
}

// ---------------- LayerNorm(x + y), shuffle reductions, fused fp16 convert ----------------
__global__ void ln_kernel(const float* __restrict__ X, const float* __restrict__ Y,
                          const float* __restrict__ gam, const float* __restrict__ bet,
                          float* __restrict__ out,
                          __half* __restrict__ oh, __half* __restrict__ ph)
{
    int row = blockIdx.x;
    int tid = threadIdx.x, wid = tid >> 5, lane = tid & 31;
    const float* x = X + row*HH;
    const float* y = Y + row*HH;
    float v[4];
    float s = 0.f;
    #pragma unroll
    for (int i = 0; i < 4; i++) { v[i] = x[tid + i*256] + y[tid + i*256]; s += v[i]; }
    #pragma unroll
    for (int off = 16; off > 0; off >>= 1) s += __shfl_xor_sync(0xFFFFFFFFu, s, off);
    __shared__ float red[8], red2[8];
    if (lane == 0) red[wid] = s;
    __syncthreads();
    float tot = 0.f;
    #pragma unroll
    for (int wdx = 0; wdx < 8; wdx++) tot += red[wdx];
    float mean = tot * (1.f/1024.f);
    float q = 0.f;
    #pragma unroll
    for (int i = 0; i < 4; i++) { float d = v[i] - mean; q = fmaf(d, d, q); }
    #pragma unroll
    for (int off = 16; off > 0; off >>= 1) q += __shfl_xor_sync(0xFFFFFFFFu, q, off);
    if (lane == 0) red2[wid] = q;
    __syncthreads();
    float tq = 0.f;
    #pragma unroll
    for (int wdx = 0; wdx < 8; wdx++) tq += red2[wdx];
    float inv = rsqrtf(tq * (1.f/1024.f) + 1e-5f);
    #pragma unroll
    for (int i = 0; i < 4; i++) {
        int c = tid + i*256;
        float o = (v[i] - mean) * inv * gam[c] + bet[c];
        out[row*HH + c] = o;
        __half hv = __float2half(o);
        oh[row*HH + c] = hv;
        if (ph) ph[row*HH + c] = hv;
    }
}

// ---------------- r = sigmoid(hf @ Wr), [s][b] layout ----------------
__global__ void r_kernel(const float* __restrict__ h, const float* __restrict__ Wr,
                         float* __restrict__ out_r, int i)
{
    int b = blockIdx.x;
    int tid = threadIdx.x, wid = tid >> 5, lane = tid & 31;
    float acc = 0.f;
    for (int k = tid; k < SQ*HH; k += 256) {
        int s = k >> 10;
        acc = fmaf(h[s*RS + b*HH + (k & 1023)], Wr[k], acc);
    }
    #pragma unroll
    for (int off = 16; off > 0; off >>= 1) acc += __shfl_xor_sync(0xFFFFFFFFu, acc, off);
    __shared__ float red[8];
    if (lane == 0) red[wid] = acc;
    __syncthreads();
    if (tid == 0) {
        float t = 0.f;
        #pragma unroll
        for (int wdx = 0; wdx < 8; wdx++) t += red[wdx];
        out_r[b*TACT + i] = 1.f / (1.f + expf(-t));
    }
}

// ---------------- s_new partials: split-K 32 (one s-position per y-block) ----------------
__global__ void snew_kernel(const float* __restrict__ h, const float* __restrict__ Wso,
                            float* __restrict__ spart)
{
    __shared__ float As[32][36];
    __shared__ float Bs[32][64];
    int tid = threadIdx.x;
    int n0 = blockIdx.x << 6;
    int k0 = blockIdx.y << 10;
    int sblk = blockIdx.y;
    int col = tid & 63;
    int rg  = tid >> 6;
    int ar = tid >> 3, ac4 = (tid & 7) << 2;
    float acc[8] = {};
    for (int kc = 0; kc < 1024; kc += 32) {
        float4 av = *(const float4*)(h + sblk*RS + ar*HH + kc + ac4);
        As[ar][ac4+0] = av.x; As[ar][ac4+1] = av.y;
        As[ar][ac4+2] = av.z; As[ar][ac4+3] = av.w;
        #pragma unroll
        for (int t = 0; t < 2; t++) {
            int f = tid + t*256;
            int kk = f >> 4, c4 = (f & 15) << 2;
            *(float4*)&Bs[kk][c4] = *(const float4*)(Wso + (size_t)(k0 + kc + kk)*HIN + n0 + c4);
        }
        __syncthreads();
        #pragma unroll 8
        for (int kk = 0; kk < 32; kk++) {
            float bv = Bs[kk][col];
            #pragma unroll
            for (int r8 = 0; r8 < 8; r8++)
                acc[r8] = fmaf(As[rg*8 + r8][kk], bv, acc[r8]);
        }
        __syncthreads();
    }
    #pragma unroll
    for (int r8 = 0; r8 < 8; r8++)
        spart[blockIdx.y*(NB*HIN) + (rg*8 + r8)*HIN + n0 + col] = acc[r8];
}

__global__ void fin_kernel(const float* __restrict__ spart, float* __restrict__ srelu,
                           float* __restrict__ out_s, int i)
{
    int idx = blockIdx.x*256 + threadIdx.x;   // 16384
    float v = 0.f;
    #pragma unroll
    for (int p = 0; p < 32; p++) v += spart[p*(NB*HIN) + idx];
    v = fmaxf(v, 0.f);
    srelu[idx] = v;
    int b = idx >> 9, n = idx & 511;
    out_s[(b*TACT + i)*HIN + n] = v;
}

// ---------------- host orchestration ----------------
extern "C" void kernel_launch(void* const* d_in, const int* in_sizes, int n_in,
                              void* d_out, int out_size)
{
    const float* history_s = (const float*)d_in[0];
    const float* history_a = (const float*)d_in[1];
    const float* s_in      = (const float*)d_in[2];
    const float* a_list    = (const float*)d_in[3];
    const float* Ws        = (const float*)d_in[4];
    const float* Wa        = (const float*)d_in[5];
    const float* Wq        = (const float*)d_in[6];
    const float* Wk        = (const float*)d_in[7];
    const float* Wv        = (const float*)d_in[8];
    const float* Wo        = (const float*)d_in[9];
    const float* Wfc       = (const float*)d_in[10];
    const float* ln1_g     = (const float*)d_in[11];
    const float* ln1_b     = (const float*)d_in[12];
    const float* ln2_g     = (const float*)d_in[13];
    const float* ln2_b     = (const float*)d_in[14];
    const float* Wr        = (const float*)d_in[15];
    const float* Wso       = (const float*)d_in[16];

    float* out_r = (float*)d_out;             // [B, TA]
    float* out_s = out_r + NB*TACT;           // [B, TA, HIN]

    void* p;
    cudaGetSymbolAddress(&p, g_pe);     float* pe     = (float*)p;
    cudaGetSymbolAddress(&p, g_tokens); float* tokens = (float*)p;
    cudaGetSymbolAddress(&p, g_h);      float* h      = (float*)p;
    cudaGetSymbolAddress(&p, g_qbuf);   float* qbuf   = (float*)p;
    cudaGetSymbolAddress(&p, g_kbig);   float* kbig   = (float*)p;
    cudaGetSymbolAddress(&p, g_vbuf);   float* vb     = (float*)p;
    cudaGetSymbolAddress(&p, g_tmp);    float* tmp    = (float*)p;
    cudaGetSymbolAddress(&p, g_spart);  float* spart  = (float*)p;
    cudaGetSymbolAddress(&p, g_srelu);  float* srelu  = (float*)p;
    cudaGetSymbolAddress(&p, g_hh);     __half* hh   = (__half*)p;
    cudaGetSymbolAddress(&p, g_ctxh);   __half* ctxh = (__half*)p;
    cudaGetSymbolAddress(&p, g_phh);    __half* phh  = (__half*)p;
    cudaGetSymbolAddress(&p, g_WhT);    __half* WhT  = (__half*)p;
    cudaGetSymbolAddress(&p, g_WlT);    __half* WlT  = (__half*)p;

    cudaFuncSetAttribute(gemm_tc,   cudaFuncAttributeMaxDynamicSharedMemorySize, GEMM_SMEM);
    cudaFuncSetAttribute(gemm_qkv3, cudaFuncAttributeMaxDynamicSharedMemorySize, GEMM_SMEM);
    cudaFuncSetAttribute(gemm_qk,   cudaFuncAttributeMaxDynamicSharedMemorySize, GEMM_SMEM);

    // side stream + events (fork-join; captured into the graph)
    cudaStream_t s2;
    cudaStreamCreate(&s2);
    cudaEvent_t evLn2[NLAY], evQK[NLAY], evR;
    for (int j = 0; j < NLAY; j++) {
        cudaEventCreateWithFlags(&evLn2[j], cudaEventDisableTiming);
        cudaEventCreateWithFlags(&evQK[j],  cudaEventDisableTiming);
    }
    cudaEventCreateWithFlags(&evR, cudaEventDisableTiming);

    pe_kernel<<<SQ, 256>>>(pe);
    zero4_kernel<<<TOK_ELEMS/1024, 256>>>(tokens);
    wconv_kernel<<<dim3(32, 32, 20), 256>>>(Wq, Wk, Wv, Wo, Wfc, WhT, WlT);

    vecmat_relu<<<dim3(NB*THIST, 4), 256>>>(history_s, HIN, Ws, HIN, 1, 0, tokens);
    vecmat_relu<<<dim3(NB*THIST, 4), 256>>>(history_a, AIN, Wa, AIN, 2, 0, tokens);
    vecmat_relu<<<dim3(NB, 4), 256>>>(s_in, HIN, Ws, HIN, 3, 16, tokens);

    for (int i = 0; i < TACT; i++) {
        int posA = 2*THIST + 1 + 2*i;
        int L = posA + 1;
        int M = NB * L;                 // valid rows (prefix)
        int Mt = (M + 127) >> 7;        // 128-row M-tiles this step
        vecmat_relu<<<dim3(NB, 4), 256>>>(a_list + i*AIN, TACT*AIN, Wa, AIN, 3, posA, tokens);
        if (i > 0) cudaStreamWaitEvent(0, evR, 0);   // r of prev step reads h
        addpe_kernel<<<TOK_ELEMS/256, 256>>>(tokens, pe, h, hh, L);

        for (int j = 0; j < NLAY; j++) {
            float* qbj = qbuf + (size_t)j*TOK_ELEMS;
            float* kbj = kbig + (size_t)j*TOK_ELEMS;
            size_t sq = (size_t)(0*4 + j)*WMAT, sk = (size_t)(1*4 + j)*WMAT;
            size_t sv = (size_t)(2*4 + j)*WMAT, so = (size_t)(3*4 + j)*WMAT;
            size_t sf = (size_t)(4*4 + j)*WMAT;

            if (i == 0) {
                gemm_qkv3<<<dim3(8, Mt, 3), 256, GEMM_SMEM>>>(hh, WhT, WlT,
                                                              sq, sk, sv, qbj, kbj, vb, M);
            } else {
                gemm_tc<<<dim3(8, Mt), 256, GEMM_SMEM>>>(hh, WhT + sv, WlT + sv, vb, M);
                cudaStreamWaitEvent(0, evQK[j], 0);     // Q/K precomputed last step
            }
            attn_kernel<<<NB*NHEAD, 256>>>(L, qbj, kbj, vb, ctxh);
            gemm_tc<<<dim3(8, Mt), 256, GEMM_SMEM>>>(ctxh, WhT + so, WlT + so, tmp, M);
            ln_kernel<<<M, 256>>>(h, tmp, ln1_g + j*HH, ln1_b + j*HH, h, hh, (__half*)0);
            gemm_tc<<<dim3(8, Mt), 256, GEMM_SMEM>>>(hh, WhT + sf, WlT + sf, tmp, M);
            ln_kernel<<<M, 256>>>(h, tmp, ln2_g + j*HH, ln2_b + j*HH, h, hh,
                                  phh + (size_t)j*TOK_ELEMS);
            cudaEventRecord(evLn2[j], 0);

            if (i + 1 < TACT) {
                // look-ahead Q/K for next step on the side stream (M+64 rows; pad zero-filled)
                cudaStreamWaitEvent(s2, evLn2[j], 0);
                int Mt2 = (M + 64 + 127) >> 7;
                gemm_qk<<<dim3(8, Mt2, 2), 256, GEMM_SMEM, s2>>>(
                    phh + (size_t)j*TOK_ELEMS, WhT, WlT, sq, sk, qbj, kbj, M);
                cudaEventRecord(evQK[j], s2);
            }
        }
        // r on the side stream (off critical path); snew/fin on main
        if (i + 1 >= TACT) cudaStreamWaitEvent(s2, evLn2[NLAY-1], 0);
        r_kernel<<<NB, 256, 0, s2>>>(h, Wr, out_r, i);
        cudaEventRecord(evR, s2);
        snew_kernel<<<dim3(8, 32), 256>>>(h, Wso, spart);
        fin_kernel<<<64, 256>>>(spart, srelu, out_s, i);
        if (i + 1 < TACT)
            vecmat_relu<<<dim3(NB, 4), 256>>>(srelu, HIN, Ws, HIN, 3, posA + 1, tokens);
    }
    cudaStreamWaitEvent(0, evR, 0);   // join side stream before returning

    for (int j = 0; j < NLAY; j++) {
        cudaEventDestroy(evLn2[j]);
        cudaEventDestroy(evQK[j]);
    }
    cudaEventDestroy(evR);
    cudaStreamDestroy(s2);
}

// round 11
// speedup vs baseline: 1.1633x; 1.1633x over previous
#include <cuda_runtime.h>
#include <cuda_fp16.h>
#include <cstdint>
#include <math.h>

#define NB    32
#define SQ    32
#define HH    1024
#define NHEAD 16
#define HS    64
#define NLAY  4
#define THIST 8
#define TACT  8
#define HIN   512
#define AIN   64
#define RS    (NB*HH)          // 32768: row stride between s-positions

#define TOK_ELEMS (NB*SQ*HH)   // 1048576
#define WMAT      (HH*HH)      // 1048576

// token row layout: row = s*NB + b  (valid rows are prefix [0, 32*L))

// ---------------- scratch (device globals; no allocation) ----------------
__device__ float g_pe[SQ*HH];
__device__ float g_tokens[TOK_ELEMS];
__device__ float g_h[TOK_ELEMS];
__device__ float g_qbuf[NLAY*TOK_ELEMS];   // per-layer Q
__device__ float g_kbig[NLAY*TOK_ELEMS];   // per-layer K
__device__ float g_vbuf[TOK_ELEMS];
__device__ float g_tmp[TOK_ELEMS];
__device__ float g_spart[32*NB*HIN];
__device__ float g_srelu[NB*HIN];
__device__ __half g_hh[TOK_ELEMS];                 // fp16 activations
__device__ __half g_ctxh[TOK_ELEMS];
__device__ __half g_phh[NLAY*TOK_ELEMS];
__device__ __half g_WhT[20*WMAT];                  // fp16 weight hi [N,K]
__device__ __half g_WlT[20*WMAT];                  // fp16 weight lo [N,K]

// ---------------- helpers ----------------
__device__ __forceinline__ uint32_t s2u(const void* p) {
    uint32_t a;
    asm("{ .reg .u64 t; cvta.to.shared.u64 t, %1; cvt.u32.u64 %0, t; }" : "=r"(a) : "l"(p));
    return a;
}

#define LDM4(r, addr) \
    asm volatile("ldmatrix.sync.aligned.m8n8.x4.shared.b16 {%0,%1,%2,%3}, [%4];" \
        : "=r"((r)[0]), "=r"((r)[1]), "=r"((r)[2]), "=r"((r)[3]) : "r"(addr))

#define MMA_F16(d, a, b0v, b1v) \
    asm volatile("mma.sync.aligned.m16n8k16.row.col.f32.f16.f16.f32 " \
        "{%0,%1,%2,%3}, {%4,%5,%6,%7}, {%8,%9}, {%0,%1,%2,%3};" \
        : "+f"((d)[0]), "+f"((d)[1]), "+f"((d)[2]), "+f"((d)[3]) \
        : "r"((a)[0]), "r"((a)[1]), "r"((a)[2]), "r"((a)[3]), "r"(b0v), "r"(b1v))

#define CP_ASYNC16(sa, gp) \
    asm volatile("cp.async.cg.shared.global [%0], [%1], 16;" :: "r"(sa), "l"(gp))
#define CP_ASYNC16Z(sa, gp, sz) \
    asm volatile("cp.async.cg.shared.global [%0], [%1], 16, %2;" :: "r"(sa), "l"(gp), "r"(sz))
#define CP_COMMIT()  asm volatile("cp.async.commit_group;" ::: "memory")
#define CP_WAIT0()   asm volatile("cp.async.wait_group 0;" ::: "memory")
#define CP_WAIT1()   asm volatile("cp.async.wait_group 1;" ::: "memory")
#define CP_WAIT2()   asm volatile("cp.async.wait_group 2;" ::: "memory")

// ---------------- weight transpose + fp16 split: W[K,N] -> WT[N,K] hi/lo ----------------
__global__ void wconv_kernel(const float* __restrict__ Wq, const float* __restrict__ Wk,
                             const float* __restrict__ Wv, const float* __restrict__ Wo,
                             const float* __restrict__ Wfc,
                             __half* __restrict__ WhT, __half* __restrict__ WlT)
{
    int z = blockIdx.z;                 // 0..19 = type*4 + layer
    int type = z >> 2, layer = z & 3;
    const float* bases[5] = {Wq, Wk, Wv, Wo, Wfc};
    const float* W = bases[type] + (size_t)layer * WMAT;
    __shared__ float t[32][33];
    int x0 = blockIdx.x * 32;  // K
    int y0 = blockIdx.y * 32;  // N
    int tr = threadIdx.x >> 5, tc = threadIdx.x & 31;
    #pragma unroll
    for (int u = 0; u < 4; u++) {
        int r = tr + u * 8;
        t[r][tc] = W[(size_t)(x0 + r) * HH + y0 + tc];
    }
    __syncthreads();
    size_t ob = (size_t)z * WMAT;
    #pragma unroll
    for (int u = 0; u < 4; u++) {
        int r = tr + u * 8;
        float v = t[tc][r];
        __half hi = __float2half(v);
        __half lo = __float2half(v - __half2float(hi));
        size_t off = ob + (size_t)(y0 + r) * HH + x0 + tc;
        WhT[off] = hi;
        WlT[off] = lo;
    }
}

// ---------------- fp16 2-term tensor-core GEMM (mma.sync) ----------------
// C[M,1024] = A x (Wh + Wl)^T.  A fp16 [M,K]; W stored [N,K] hi/lo.
// CTA tile 64(M) x 128(N), K-chunk 64, 4-buffer/3-outstanding cp.async pipeline.
// Stage (40960 B): A[0,8K) Bh[8K,24K) Bl[24K,40K)
#define STAGE 40960
#define NBUF  4
#define GEMM_SMEM (NBUF*STAGE)    // 163840

__device__ __forceinline__ void issue_stage(uint32_t sbase, int buf,
    const __half* __restrict__ A,
    const __half* __restrict__ Bh, const __half* __restrict__ Bl,
    int bm, int bn, int k0, int tid, int mvalid)
{
    uint32_t st = sbase + buf * STAGE;
    #pragma unroll
    for (int u = 0; u < 10; u++) {
        int id = tid + u * 256;
        if (id < 512) {
            int r = id >> 3, c = id & 7;
            const __half* gp = A + (size_t)(bm + r) * HH + k0 + c * 8;
            uint32_t sa = st + r * 128 + ((c ^ (r & 7)) << 4);
            uint32_t sz = ((bm + r) < mvalid) ? 16u : 0u;
            CP_ASYNC16Z(sa, gp, sz);
        } else {
            int sec = (id - 512) >> 10;      // 0=Bh 1=Bl
            int t = (id - 512) & 1023;
            int r = t >> 3, c = t & 7;
            const __half* gp = (sec ? Bl : Bh) + (size_t)(bn + r) * HH + k0 + c * 8;
            uint32_t sa = st + 8192 + sec * 16384 + r * 128 + ((c ^ (r & 7)) << 4);
            CP_ASYNC16(sa, gp);
        }
    }
    CP_COMMIT();
}

__device__ __forceinline__ void gemm_body(
    const __half* __restrict__ A,
    const __half* __restrict__ Bh, const __half* __restrict__ Bl,
    float* __restrict__ C, int mvalid)
{
    extern __shared__ char smem[];
    uint32_t sbase = s2u(smem);
    int tid = threadIdx.x, wid = tid >> 5, lane = tid & 31;
    int bm = blockIdx.y << 6, bn = blockIdx.x << 7;
    int warpM = (wid >> 2) << 5;
    int warpN = (wid & 3) << 5;

    issue_stage(sbase, 0, A, Bh, Bl, bm, bn, 0,   tid, mvalid);
    issue_stage(sbase, 1, A, Bh, Bl, bm, bn, 64,  tid, mvalid);
    issue_stage(sbase, 2, A, Bh, Bl, bm, bn, 128, tid, mvalid);

    float acc[2][4][4] = {};

    for (int s = 0; s < 16; s++) {
        if (s < 14)       { CP_WAIT2(); }
        else if (s == 14) { CP_WAIT1(); }
        else              { CP_WAIT0(); }
        __syncthreads();
        if (s + 3 < 16)
            issue_stage(sbase, (s + 3) & 3, A, Bh, Bl, bm, bn, (s + 3) << 6, tid, mvalid);
        uint32_t st = sbase + (s & 3) * STAGE;
        #pragma unroll
        for (int kk = 0; kk < 4; kk++) {
            uint32_t ah[2][4];
            #pragma unroll
            for (int mt = 0; mt < 2; mt++) {
                int r = warpM + mt * 16 + (lane & 15);
                int ch = kk * 2 + (lane >> 4);
                uint32_t ad = st + r * 128 + ((ch ^ (r & 7)) << 4);
                LDM4(ah[mt], ad);
            }
            uint32_t bh[2][4], bl[2][4];
            #pragma unroll
            for (int nt = 0; nt < 2; nt++) {
                int r = warpN + nt * 16 + (lane & 7) + ((lane >> 4) << 3);
                int ch = kk * 2 + ((lane >> 3) & 1);
                uint32_t bd = st + 8192 + r * 128 + ((ch ^ (r & 7)) << 4);
                LDM4(bh[nt], bd);
                LDM4(bl[nt], bd + 16384);
            }
            #pragma unroll
            for (int mt = 0; mt < 2; mt++) {
                #pragma unroll
                for (int j = 0; j < 4; j++) {
                    uint32_t b0 = bh[j >> 1][(j & 1) * 2], b1 = bh[j >> 1][(j & 1) * 2 + 1];
                    uint32_t c0 = bl[j >> 1][(j & 1) * 2], c1 = bl[j >> 1][(j & 1) * 2 + 1];
                    MMA_F16(acc[mt][j], ah[mt], b0, b1);
                    MMA_F16(acc[mt][j], ah[mt], c0, c1);
                }
            }
        }
    }

    #pragma unroll
    for (int mt = 0; mt < 2; mt++) {
        int row = bm + warpM + mt * 16 + (lane >> 2);
        #pragma unroll
        for (int j = 0; j < 4; j++) {
            int col = bn + warpN + j * 8 + ((lane & 3) << 1);
            *(float2*)&C[(size_t)row * HH + col] =
                make_float2(acc[mt][j][0], acc[mt][j][1]);
            *(float2*)&C[(size_t)(row + 8) * HH + col] =
                make_float2(acc[mt][j][2], acc[mt][j][3]);
        }
    }
}

__global__ void __launch_bounds__(256, 1) gemm_tc(
    const __half* __restrict__ A,
    const __half* __restrict__ Bh, const __half* __restrict__ Bl,
    float* __restrict__ C, int mvalid)
{
    gemm_body(A, Bh, Bl, C, mvalid);
}

// step-0 QKV: all operands from current hh
__global__ void __launch_bounds__(256, 1) gemm_qkv3(
    const __half* __restrict__ hh,
    const __half* __restrict__ WhT, const __half* __restrict__ WlT,
    size_t sq, size_t sk, size_t sv,
    float* __restrict__ Q, float* __restrict__ K, float* __restrict__ V, int mvalid)
{
    int z = blockIdx.z;
    size_t off = (z == 0) ? sq : (z == 1) ? sk : sv;
    float* C = (z == 0) ? Q : (z == 1) ? K : V;
    gemm_body(hh, WhT + off, WlT + off, C, mvalid);
}

// look-ahead Q,K for next step from prev_h[j]
__global__ void __launch_bounds__(256, 1) gemm_qk(
    const __half* __restrict__ ph,
    const __half* __restrict__ WhT, const __half* __restrict__ WlT,
    size_t sq, size_t sk,
    float* __restrict__ Q, float* __restrict__ K, int mvalid)
{
    int z = blockIdx.z;
    size_t off = (z == 0) ? sq : sk;
    float* C = (z == 0) ? Q : K;
    gemm_body(ph, WhT + off, WlT + off, C, mvalid);
}

// ---------------- positional encoding ----------------
__global__ void pe_kernel(float* __restrict__ pe)
{
    int s = blockIdx.x;
    for (int h = threadIdx.x; h < HH; h += 256) {
        float e = (float)(2 * (h / 2)) * (1.0f / HH);
        float freq = exp2f(-e * 13.287712379549449f);   // log2(10000)
        float angle = (float)s * freq;
        pe[s*HH + h] = (h & 1) ? cosf(angle) : sinf(angle);
    }
}

__global__ void zero4_kernel(float* __restrict__ p)
{
    int idx = blockIdx.x*256 + threadIdx.x;
    ((float4*)p)[idx] = make_float4(0.f,0.f,0.f,0.f);
}

// ---------------- small row GEMM + relu into tokens ([s][b] layout) ----------------
// unrolled 8-wide accumulation (MLP ~8, was latency-serialized)
// mode 1: history_s rows; mode 2: history_a rows; mode 3: single token row 'off';
// mode 4: ALL action tokens (r = b*TACT + t -> row (2*TH+1+2t)*NB + b)
__global__ void vecmat_relu(const float* __restrict__ X, int xstride,
                            const float* __restrict__ W, int K,
                            int mode, int off, float* __restrict__ tokens)
{
    int r = blockIdx.x;
    __shared__ float xs[512];
    for (int k = threadIdx.x; k < K; k += 256) xs[k] = X[(size_t)r*xstride + k];
    __syncthreads();
    int drow;
    if      (mode == 1) drow = (2*(r&7))*NB + (r>>3);
    else if (mode == 2) drow = (2*(r&7)+1)*NB + (r>>3);
    else if (mode == 4) drow = (2*THIST + 1 + 2*(r % TACT))*NB + (r / TACT);
    else                drow = off*NB + r;
    int c = blockIdx.y*256 + threadIdx.x;
    float a[8] = {};
    for (int k = 0; k < K; k += 8) {
        #pragma unroll
        for (int u = 0; u < 8; u++)
            a[u] = fmaf(xs[k + u], W[(k + u)*HH + c], a[u]);
    }
    float acc = ((a[0]+a[1]) + (a[2]+a[3])) + ((a[4]+a[5]) + (a[6]+a[7]));
    tokens[drow*HH + c] = fmaxf(acc, 0.f);
}

// ---------------- h = tokens + pe (valid rows; pad rows forced to 0) ----------------
__global__ void addpe_kernel(const float* __restrict__ tokens,
                             const float* __restrict__ pe,
                             float* __restrict__ h,
                             __half* __restrict__ hh, int L)
{
    int i = blockIdx.x*256 + threadIdx.x;
    int srow = i >> 15;                       // s index ([s][b] layout)
    float v = 0.f;
    if (srow < L) v = tokens[i] + pe[srow*HH + (i & 1023)];
    h[i] = v;
    hh[i] = __float2half(v);
}

// ---------------- attention (one block per (b, head)), [s][b] layout ----------------
__global__ void attn_kernel(int L, const float* __restrict__ Q,
                            const float* __restrict__ K,
                            const float* __restrict__ V,
                            __half* __restrict__ ctxh)
{
    __shared__ float Qs[32][64];
    __shared__ float KsT[64][33];
    __shared__ float Vs[32][64];
    __shared__ float P[32][33];
    int tid = threadIdx.x;
    int b = blockIdx.x >> 4, hd = blockIdx.x & 15;
    const float* qb = Q + b*HH + hd*HS;
    const float* kb = K + b*HH + hd*HS;
    const float* vb = V + b*HH + hd*HS;
    #pragma unroll
    for (int t = 0; t < 2; t++) {
        int f = tid + t*256;
        int row = f >> 4, c4 = (f & 15) << 2;
        float4 q4 = *(const float4*)(qb + row*RS + c4);
        *(float4*)&Qs[row][c4] = q4;
        float4 k4 = *(const float4*)(kb + row*RS + c4);
        KsT[c4+0][row] = k4.x; KsT[c4+1][row] = k4.y;
        KsT[c4+2][row] = k4.z; KsT[c4+3][row] = k4.w;
        float4 v4 = *(const float4*)(vb + row*RS + c4);
        *(float4*)&Vs[row][c4] = v4;
    }
    __syncthreads();
    #pragma unroll
    for (int t = 0; t < 4; t++) {
        int p = tid + t*256;
        int qr = p >> 5, kr = p & 31;
        float sc = 0.f;
        #pragma unroll
        for (int d = 0; d < 64; d++) sc = fmaf(Qs[qr][d], KsT[d][kr], sc);
        P[qr][kr] = sc * 0.125f;
    }
    __syncthreads();
    int w = tid >> 5, lane = tid & 31;
    #pragma unroll
    for (int r = 0; r < 4; r++) {
        int qr = w + r*8;
        bool vq = qr < L, vk = lane < L;
        float v = (vq && vk) ? P[qr][lane] : -1e30f;
        float mx = v;
        #pragma unroll
        for (int off = 16; off > 0; off >>= 1)
            mx = fmaxf(mx, __shfl_xor_sync(0xFFFFFFFFu, mx, off));
        float e = (vq && vk) ? expf(v - mx) : 0.f;
        float sm = e;
        #pragma unroll
        for (int off = 16; off > 0; off >>= 1)
            sm += __shfl_xor_sync(0xFFFFFFFFu, sm, off);
        P[qr][lane] = vq ? (e / sm) : 0.f;
    }
    __syncthreads();
    __half* ch = ctxh + b*HH + hd*HS;
    #pragma unroll
    for (int t = 0; t < 8; t++) {
        int e = tid + t*256;
        int qr = e >> 6, d = e & 63;
        float acc = 0.f;
        #pragma unroll
        for (int k = 0; k < 32; k++) acc = fmaf(P[qr][k], Vs[k][d], acc);
        ch[qr*RS + d] = __float2half(acc);
    }
}

// ---------------- LayerNorm(x + y), shuffle reductions, fused fp16 convert ----------------
__global__ void ln_kernel(const float* __restrict__ X, const float* __restrict__ Y,
                          const float* __restrict__ gam, const float* __restrict__ bet,
                          float* __restrict__ out,
                          __half* __restrict__ oh, __half* __restrict__ ph)
{
    int row = blockIdx.x;
    int tid = threadIdx.x, wid = tid >> 5, lane = tid & 31;
    const float* x = X + row*HH;
    const float* y = Y + row*HH;
    float v[4];
    float s = 0.f;
    #pragma unroll
    for (int i = 0; i < 4; i++) { v[i] = x[tid + i*256] + y[tid + i*256]; s += v[i]; }
    #pragma unroll
    for (int off = 16; off > 0; off >>= 1) s += __shfl_xor_sync(0xFFFFFFFFu, s, off);
    __shared__ float red[8], red2[8];
    if (lane == 0) red[wid] = s;
    __syncthreads();
    float tot = 0.f;
    #pragma unroll
    for (int wdx = 0; wdx < 8; wdx++) tot += red[wdx];
    float mean = tot * (1.f/1024.f);
    float q = 0.f;
    #pragma unroll
    for (int i = 0; i < 4; i++) { float d = v[i] - mean; q = fmaf(d, d, q); }
    #pragma unroll
    for (int off = 16; off > 0; off >>= 1) q += __shfl_xor_sync(0xFFFFFFFFu, q, off);
    if (lane == 0) red2[wid] = q;
    __syncthreads();
    float tq = 0.f;
    #pragma unroll
    for (int wdx = 0; wdx < 8; wdx++) tq += red2[wdx];
    float inv = rsqrtf(tq * (1.f/1024.f) + 1e-5f);
    #pragma unroll
    for (int i = 0; i < 4; i++) {
        int c = tid + i*256;
        float o = (v[i] - mean) * inv * gam[c] + bet[c];
        out[row*HH + c] = o;
        __half hv = __float2half(o);
        oh[row*HH + c] = hv;
        if (ph) ph[row*HH + c] = hv;
    }
}

// ---------------- r = sigmoid(hf @ Wr), [s][b] layout ----------------
__global__ void r_kernel(const float* __restrict__ h, const float* __restrict__ Wr,
                         float* __restrict__ out_r, int i)
{
    int b = blockIdx.x;
    int tid = threadIdx.x, wid = tid >> 5, lane = tid & 31;
    float acc = 0.f;
    for (int k = tid; k < SQ*HH; k += 256) {
        int s = k >> 10;
        acc = fmaf(h[s*RS + b*HH + (k & 1023)], Wr[k], acc);
    }
    #pragma unroll
    for (int off = 16; off > 0; off >>= 1) acc += __shfl_xor_sync(0xFFFFFFFFu, acc, off);
    __shared__ float red[8];
    if (lane == 0) red[wid] = acc;
    __syncthreads();
    if (tid == 0) {
        float t = 0.f;
        #pragma unroll
        for (int wdx = 0; wdx < 8; wdx++) t += red[wdx];
        out_r[b*TACT + i] = 1.f / (1.f + expf(-t));
    }
}

// ---------------- s_new partials: split-K 32 (one s-position per y-block) ----------------
__global__ void snew_kernel(const float* __restrict__ h, const float* __restrict__ Wso,
                            float* __restrict__ spart)
{
    __shared__ float As[32][36];
    __shared__ float Bs[32][64];
    int tid = threadIdx.x;
    int n0 = blockIdx.x << 6;
    int k0 = blockIdx.y << 10;
    int sblk = blockIdx.y;
    int col = tid & 63;
    int rg  = tid >> 6;
    int ar = tid >> 3, ac4 = (tid & 7) << 2;
    float acc[8] = {};
    for (int kc = 0; kc < 1024; kc += 32) {
        float4 av = *(const float4*)(h + sblk*RS + ar*HH + kc + ac4);
        As[ar][ac4+0] = av.x; As[ar][ac4+1] = av.y;
        As[ar][ac4+2] = av.z; As[ar][ac4+3] = av.w;
        #pragma unroll
        for (int t = 0; t < 2; t++) {
            int f = tid + t*256;
            int kk = f >> 4, c4 = (f & 15) << 2;
            *(float4*)&Bs[kk][c4] = *(const float4*)(Wso + (size_t)(k0 + kc + kk)*HIN + n0 + c4);
        }
        __syncthreads();
        #pragma unroll 8
        for (int kk = 0; kk < 32; kk++) {
            float bv = Bs[kk][col];
            #pragma unroll
            for (int r8 = 0; r8 < 8; r8++)
                acc[r8] = fmaf(As[rg*8 + r8][kk], bv, acc[r8]);
        }
        __syncthreads();
    }
    #pragma unroll
    for (int r8 = 0; r8 < 8; r8++)
        spart[blockIdx.y*(NB*HIN) + (rg*8 + r8)*HIN + n0 + col] = acc[r8];
}

__global__ void fin_kernel(const float* __restrict__ spart, float* __restrict__ srelu,
                           float* __restrict__ out_s, int i)
{
    int idx = blockIdx.x*256 + threadIdx.x;   // 16384
    float v = 0.f;
    #pragma unroll
    for (int p = 0; p < 32; p++) v += spart[p*(NB*HIN) + idx];
    v = fmaxf(v, 0.f);
    srelu[idx] = v;
    int b = idx >> 9, n = idx & 511;
    out_s[(b*TACT + i)*HIN + n] = v;
}

// ---------------- host orchestration ----------------
extern "C" void kernel_launch(void* const* d_in, const int* in_sizes, int n_in,
                              void* d_out, int out_size)
{
    const float* history_s = (const float*)d_in[0];
    const float* history_a = (const float*)d_in[1];
    const float* s_in      = (const float*)d_in[2];
    const float* a_list    = (const float*)d_in[3];
    const float* Ws        = (const float*)d_in[4];
    const float* Wa        = (const float*)d_in[5];
    const float* Wq        = (const float*)d_in[6];
    const float* Wk        = (const float*)d_in[7];
    const float* Wv        = (const float*)d_in[8];
    const float* Wo        = (const float*)d_in[9];
    const float* Wfc       = (const float*)d_in[10];
    const float* ln1_g     = (const float*)d_in[11];
    const float* ln1_b     = (const float*)d_in[12];
    const float* ln2_g     = (const float*)d_in[13];
    const float* ln2_b     = (const float*)d_in[14];
    const float* Wr        = (const float*)d_in[15];
    const float* Wso       = (const float*)d_in[16];

    float* out_r = (float*)d_out;             // [B, TA]
    float* out_s = out_r + NB*TACT;           // [B, TA, HIN]

    void* p;
    cudaGetSymbolAddress(&p, g_pe);     float* pe     = (float*)p;
    cudaGetSymbolAddress(&p, g_tokens); float* tokens = (float*)p;
    cudaGetSymbolAddress(&p, g_h);      float* h      = (float*)p;
    cudaGetSymbolAddress(&p, g_qbuf);   float* qbuf   = (float*)p;
    cudaGetSymbolAddress(&p, g_kbig);   float* kbig   = (float*)p;
    cudaGetSymbolAddress(&p, g_vbuf);   float* vb     = (float*)p;
    cudaGetSymbolAddress(&p, g_tmp);    float* tmp    = (float*)p;
    cudaGetSymbolAddress(&p, g_spart);  float* spart  = (float*)p;
    cudaGetSymbolAddress(&p, g_srelu);  float* srelu  = (float*)p;
    cudaGetSymbolAddress(&p, g_hh);     __half* hh   = (__half*)p;
    cudaGetSymbolAddress(&p, g_ctxh);   __half* ctxh = (__half*)p;
    cudaGetSymbolAddress(&p, g_phh);    __half* phh  = (__half*)p;
    cudaGetSymbolAddress(&p, g_WhT);    __half* WhT  = (__half*)p;
    cudaGetSymbolAddress(&p, g_WlT);    __half* WlT  = (__half*)p;

    cudaFuncSetAttribute(gemm_tc,   cudaFuncAttributeMaxDynamicSharedMemorySize, GEMM_SMEM);
    cudaFuncSetAttribute(gemm_qkv3, cudaFuncAttributeMaxDynamicSharedMemorySize, GEMM_SMEM);
    cudaFuncSetAttribute(gemm_qk,   cudaFuncAttributeMaxDynamicSharedMemorySize, GEMM_SMEM);

    // side stream + events (fork-join; captured into the graph)
    cudaStream_t s2;
    cudaStreamCreate(&s2);
    cudaEvent_t evLn2[NLAY], evQK[NLAY], evR;
    for (int j = 0; j < NLAY; j++) {
        cudaEventCreateWithFlags(&evLn2[j], cudaEventDisableTiming);
        cudaEventCreateWithFlags(&evQK[j],  cudaEventDisableTiming);
    }
    cudaEventCreateWithFlags(&evR, cudaEventDisableTiming);

    pe_kernel<<<SQ, 256>>>(pe);
    zero4_kernel<<<TOK_ELEMS/1024, 256>>>(tokens);
    wconv_kernel<<<dim3(32, 32, 20), 256>>>(Wq, Wk, Wv, Wo, Wfc, WhT, WlT);

    // startup token embeds: history s/a, initial state, and ALL 8 action tokens
    vecmat_relu<<<dim3(NB*THIST, 4), 256>>>(history_s, HIN, Ws, HIN, 1, 0, tokens);
    vecmat_relu<<<dim3(NB*THIST, 4), 256>>>(history_a, AIN, Wa, AIN, 2, 0, tokens);
    vecmat_relu<<<dim3(NB, 4), 256>>>(s_in, HIN, Ws, HIN, 3, 16, tokens);
    vecmat_relu<<<dim3(NB*TACT, 4), 256>>>(a_list, AIN, Wa, AIN, 4, 0, tokens);

    for (int i = 0; i < TACT; i++) {
        int posA = 2*THIST + 1 + 2*i;
        int L = posA + 1;
        int M = NB * L;                 // valid rows (prefix), divisible by 64
        int Mt = M >> 6;                // 64-row M-tiles this step
        if (i > 0) cudaStreamWaitEvent(0, evR, 0);   // r of prev step reads h
        addpe_kernel<<<TOK_ELEMS/256, 256>>>(tokens, pe, h, hh, L);

        for (int j = 0; j < NLAY; j++) {
            float* qbj = qbuf + (size_t)j*TOK_ELEMS;
            float* kbj = kbig + (size_t)j*TOK_ELEMS;
            size_t sq = (size_t)(0*4 + j)*WMAT, sk = (size_t)(1*4 + j)*WMAT;
            size_t sv = (size_t)(2*4 + j)*WMAT, so = (size_t)(3*4 + j)*WMAT;
            size_t sf = (size_t)(4*4 + j)*WMAT;

            if (i == 0) {
                gemm_qkv3<<<dim3(8, Mt, 3), 256, GEMM_SMEM>>>(hh, WhT, WlT,
                                                              sq, sk, sv, qbj, kbj, vb, M);
            } else {
                gemm_tc<<<dim3(8, Mt), 256, GEMM_SMEM>>>(hh, WhT + sv, WlT + sv, vb, M);
                cudaStreamWaitEvent(0, evQK[j], 0);     // Q/K precomputed last step
            }
            attn_kernel<<<NB*NHEAD, 256>>>(L, qbj, kbj, vb, ctxh);
            gemm_tc<<<dim3(8, Mt), 256, GEMM_SMEM>>>(ctxh, WhT + so, WlT + so, tmp, M);
            ln_kernel<<<M, 256>>>(h, tmp, ln1_g + j*HH, ln1_b + j*HH, h, hh, (__half*)0);
            gemm_tc<<<dim3(8, Mt), 256, GEMM_SMEM>>>(hh, WhT + sf, WlT + sf, tmp, M);
            ln_kernel<<<M, 256>>>(h, tmp, ln2_g + j*HH, ln2_b + j*HH, h, hh,
                                  phh + (size_t)j*TOK_ELEMS);
            cudaEventRecord(evLn2[j], 0);

            if (i + 1 < TACT) {
                // look-ahead Q/K for next step on the side stream (M+64 rows; pad zero-filled)
                cudaStreamWaitEvent(s2, evLn2[j], 0);
                gemm_qk<<<dim3(8, Mt + 1, 2), 256, GEMM_SMEM, s2>>>(
                    phh + (size_t)j*TOK_ELEMS, WhT, WlT, sq, sk, qbj, kbj, M);
                cudaEventRecord(evQK[j], s2);
            }
        }
        // r on the side stream (off critical path); snew/fin on main
        if (i + 1 >= TACT) cudaStreamWaitEvent(s2, evLn2[NLAY-1], 0);
        r_kernel<<<NB, 256, 0, s2>>>(h, Wr, out_r, i);
        cudaEventRecord(evR, s2);
        snew_kernel<<<dim3(8, 32), 256>>>(h, Wso, spart);
        fin_kernel<<<64, 256>>>(spart, srelu, out_s, i);
        if (i + 1 < TACT)
            vecmat_relu<<<dim3(NB, 4), 256>>>(srelu, HIN, Ws, HIN, 3, posA + 1, tokens);
    }
    cudaStreamWaitEvent(0, evR, 0);   // join side stream before returning

    for (int j = 0; j < NLAY; j++) {
        cudaEventDestroy(evLn2[j]);
        cudaEventDestroy(evQK[j]);
    }
    cudaEventDestroy(evR);
    cudaStreamDestroy(s2);
}

// round 13
// speedup vs baseline: 1.2391x; 1.0651x over previous
#include <cuda_runtime.h>
#include <cuda_fp16.h>
#include <cstdint>
#include <math.h>

#define NB    32
#define SQ    32
#define HH    1024
#define NHEAD 16
#define HS    64
#define NLAY  4
#define THIST 8
#define TACT  8
#define HIN   512
#define AIN   64
#define RS    (NB*HH)          // 32768: row stride between s-positions

#define TOK_ELEMS (NB*SQ*HH)   // 1048576
#define WMAT      (HH*HH)      // 1048576

// token row layout: row = s*NB + b  (valid rows are prefix [0, 32*L))

// ---------------- scratch (device globals; no allocation) ----------------
__device__ float g_pe[SQ*HH];
__device__ float g_tokens[TOK_ELEMS];
__device__ float g_h[TOK_ELEMS];
__device__ float g_qbuf[NLAY*TOK_ELEMS];   // per-layer Q
__device__ float g_kbig[NLAY*TOK_ELEMS];   // per-layer K
__device__ float g_vbuf[TOK_ELEMS];
__device__ float g_tmp[TOK_ELEMS];
__device__ float g_spart[32*NB*HIN];
__device__ float g_srelu[NB*HIN];
__device__ __half g_hh[TOK_ELEMS];                 // fp16 activations
__device__ __half g_ctxh[TOK_ELEMS];
__device__ __half g_phh[NLAY*TOK_ELEMS];
__device__ __half g_WhT[20*WMAT];                  // fp16 weight hi [N,K]
__device__ __half g_WlT[20*WMAT];                  // fp16 weight lo [N,K]

// ---------------- helpers ----------------
__device__ __forceinline__ uint32_t s2u(const void* p) {
    uint32_t a;
    asm("{ .reg .u64 t; cvta.to.shared.u64 t, %1; cvt.u32.u64 %0, t; }" : "=r"(a) : "l"(p));
    return a;
}

#define LDM4(r, addr) \
    asm volatile("ldmatrix.sync.aligned.m8n8.x4.shared.b16 {%0,%1,%2,%3}, [%4];" \
        : "=r"((r)[0]), "=r"((r)[1]), "=r"((r)[2]), "=r"((r)[3]) : "r"(addr))

#define MMA_F16(d, a, b0v, b1v) \
    asm volatile("mma.sync.aligned.m16n8k16.row.col.f32.f16.f16.f32 " \
        "{%0,%1,%2,%3}, {%4,%5,%6,%7}, {%8,%9}, {%0,%1,%2,%3};" \
        : "+f"((d)[0]), "+f"((d)[1]), "+f"((d)[2]), "+f"((d)[3]) \
        : "r"((a)[0]), "r"((a)[1]), "r"((a)[2]), "r"((a)[3]), "r"(b0v), "r"(b1v))

#define CP_ASYNC16(sa, gp) \
    asm volatile("cp.async.cg.shared.global [%0], [%1], 16;" :: "r"(sa), "l"(gp))
#define CP_ASYNC16Z(sa, gp, sz) \
    asm volatile("cp.async.cg.shared.global [%0], [%1], 16, %2;" :: "r"(sa), "l"(gp), "r"(sz))
#define CP_COMMIT()  asm volatile("cp.async.commit_group;" ::: "memory")
#define CP_WAIT0()   asm volatile("cp.async.wait_group 0;" ::: "memory")
#define CP_WAIT1()   asm volatile("cp.async.wait_group 1;" ::: "memory")
#define CP_WAIT2()   asm volatile("cp.async.wait_group 2;" ::: "memory")

// ---------------- weight transpose + fp16 split: W[K,N] -> WT[N,K] hi/lo ----------------
__global__ void wconv_kernel(const float* __restrict__ Wq, const float* __restrict__ Wk,
                             const float* __restrict__ Wv, const float* __restrict__ Wo,
                             const float* __restrict__ Wfc,
                             __half* __restrict__ WhT, __half* __restrict__ WlT)
{
    int z = blockIdx.z;                 // 0..19 = type*4 + layer
    int type = z >> 2, layer = z & 3;
    const float* bases[5] = {Wq, Wk, Wv, Wo, Wfc};
    const float* W = bases[type] + (size_t)layer * WMAT;
    __shared__ float t[32][33];
    int x0 = blockIdx.x * 32;  // K
    int y0 = blockIdx.y * 32;  // N
    int tr = threadIdx.x >> 5, tc = threadIdx.x & 31;
    #pragma unroll
    for (int u = 0; u < 4; u++) {
        int r = tr + u * 8;
        t[r][tc] = W[(size_t)(x0 + r) * HH + y0 + tc];
    }
    __syncthreads();
    size_t ob = (size_t)z * WMAT;
    #pragma unroll
    for (int u = 0; u < 4; u++) {
        int r = tr + u * 8;
        float v = t[tc][r];
        __half hi = __float2half(v);
        __half lo = __float2half(v - __half2float(hi));
        size_t off = ob + (size_t)(y0 + r) * HH + x0 + tc;
        WhT[off] = hi;
        WlT[off] = lo;
    }
}

// ---------------- fp16 2-term tensor-core GEMM (mma.sync) ----------------
// C[M,1024] = A x (Wh + Wl)^T.  A fp16 [M,K]; W stored [N,K] hi/lo.
// CTA tile 64(M) x 128(N), K-chunk 64, 4-buffer/3-outstanding cp.async pipeline.
// Stage (40960 B): A[0,8K) Bh[8K,24K) Bl[24K,40K)
#define STAGE 40960
#define NBUF  4
#define GEMM_SMEM (NBUF*STAGE)    // 163840

__device__ __forceinline__ void issue_stage(uint32_t sbase, int buf,
    const __half* __restrict__ A,
    const __half* __restrict__ Bh, const __half* __restrict__ Bl,
    int bm, int bn, int k0, int tid, int mvalid)
{
    uint32_t st = sbase + buf * STAGE;
    #pragma unroll
    for (int u = 0; u < 10; u++) {
        int id = tid + u * 256;
        if (id < 512) {
            int r = id >> 3, c = id & 7;
            const __half* gp = A + (size_t)(bm + r) * HH + k0 + c * 8;
            uint32_t sa = st + r * 128 + ((c ^ (r & 7)) << 4);
            uint32_t sz = ((bm + r) < mvalid) ? 16u : 0u;
            CP_ASYNC16Z(sa, gp, sz);
        } else {
            int sec = (id - 512) >> 10;      // 0=Bh 1=Bl
            int t = (id - 512) & 1023;
            int r = t >> 3, c = t & 7;
            const __half* gp = (sec ? Bl : Bh) + (size_t)(bn + r) * HH + k0 + c * 8;
            uint32_t sa = st + 8192 + sec * 16384 + r * 128 + ((c ^ (r & 7)) << 4);
            CP_ASYNC16(sa, gp);
        }
    }
    CP_COMMIT();
}

__device__ __forceinline__ void gemm_body(
    const __half* __restrict__ A,
    const __half* __restrict__ Bh, const __half* __restrict__ Bl,
    float* __restrict__ C, int mvalid)
{
    extern __shared__ char smem[];
    uint32_t sbase = s2u(smem);
    int tid = threadIdx.x, wid = tid >> 5, lane = tid & 31;
    int bm = blockIdx.y << 6, bn = blockIdx.x << 7;
    int warpM = (wid >> 2) << 5;
    int warpN = (wid & 3) << 5;

    issue_stage(sbase, 0, A, Bh, Bl, bm, bn, 0,   tid, mvalid);
    issue_stage(sbase, 1, A, Bh, Bl, bm, bn, 64,  tid, mvalid);
    issue_stage(sbase, 2, A, Bh, Bl, bm, bn, 128, tid, mvalid);

    float acc[2][4][4] = {};

    for (int s = 0; s < 16; s++) {
        if (s < 14)       { CP_WAIT2(); }
        else if (s == 14) { CP_WAIT1(); }
        else              { CP_WAIT0(); }
        __syncthreads();
        if (s + 3 < 16)
            issue_stage(sbase, (s + 3) & 3, A, Bh, Bl, bm, bn, (s + 3) << 6, tid, mvalid);
        uint32_t st = sbase + (s & 3) * STAGE;
        #pragma unroll
        for (int kk = 0; kk < 4; kk++) {
            uint32_t ah[2][4];
            #pragma unroll
            for (int mt = 0; mt < 2; mt++) {
                int r = warpM + mt * 16 + (lane & 15);
                int ch = kk * 2 + (lane >> 4);
                uint32_t ad = st + r * 128 + ((ch ^ (r & 7)) << 4);
                LDM4(ah[mt], ad);
            }
            uint32_t bh[2][4], bl[2][4];
            #pragma unroll
            for (int nt = 0; nt < 2; nt++) {
                int r = warpN + nt * 16 + (lane & 7) + ((lane >> 4) << 3);
                int ch = kk * 2 + ((lane >> 3) & 1);
                uint32_t bd = st + 8192 + r * 128 + ((ch ^ (r & 7)) << 4);
                LDM4(bh[nt], bd);
                LDM4(bl[nt], bd + 16384);
            }
            #pragma unroll
            for (int mt = 0; mt < 2; mt++) {
                #pragma unroll
                for (int j = 0; j < 4; j++) {
                    uint32_t b0 = bh[j >> 1][(j & 1) * 2], b1 = bh[j >> 1][(j & 1) * 2 + 1];
                    uint32_t c0 = bl[j >> 1][(j & 1) * 2], c1 = bl[j >> 1][(j & 1) * 2 + 1];
                    MMA_F16(acc[mt][j], ah[mt], b0, b1);
                    MMA_F16(acc[mt][j], ah[mt], c0, c1);
                }
            }
        }
    }

    #pragma unroll
    for (int mt = 0; mt < 2; mt++) {
        int row = bm + warpM + mt * 16 + (lane >> 2);
        #pragma unroll
        for (int j = 0; j < 4; j++) {
            int col = bn + warpN + j * 8 + ((lane & 3) << 1);
            *(float2*)&C[(size_t)row * HH + col] =
                make_float2(acc[mt][j][0], acc[mt][j][1]);
            *(float2*)&C[(size_t)(row + 8) * HH + col] =
                make_float2(acc[mt][j][2], acc[mt][j][3]);
        }
    }
}

__global__ void __launch_bounds__(256, 1) gemm_tc(
    const __half* __restrict__ A,
    const __half* __restrict__ Bh, const __half* __restrict__ Bl,
    float* __restrict__ C, int mvalid)
{
    gemm_body(A, Bh, Bl, C, mvalid);
}

// step-0 QKV: all operands from current hh
__global__ void __launch_bounds__(256, 1) gemm_qkv3(
    const __half* __restrict__ hh,
    const __half* __restrict__ WhT, const __half* __restrict__ WlT,
    size_t sq, size_t sk, size_t sv,
    float* __restrict__ Q, float* __restrict__ K, float* __restrict__ V, int mvalid)
{
    int z = blockIdx.z;
    size_t off = (z == 0) ? sq : (z == 1) ? sk : sv;
    float* C = (z == 0) ? Q : (z == 1) ? K : V;
    gemm_body(hh, WhT + off, WlT + off, C, mvalid);
}

// look-ahead Q,K for next step from prev_h[j]
__global__ void __launch_bounds__(256, 1) gemm_qk(
    const __half* __restrict__ ph,
    const __half* __restrict__ WhT, const __half* __restrict__ WlT,
    size_t sq, size_t sk,
    float* __restrict__ Q, float* __restrict__ K, int mvalid)
{
    int z = blockIdx.z;
    size_t off = (z == 0) ? sq : sk;
    float* C = (z == 0) ? Q : K;
    gemm_body(ph, WhT + off, WlT + off, C, mvalid);
}

// ---------------- positional encoding ----------------
__global__ void pe_kernel(float* __restrict__ pe)
{
    int s = blockIdx.x;
    for (int h = threadIdx.x; h < HH; h += 256) {
        float e = (float)(2 * (h / 2)) * (1.0f / HH);
        float freq = exp2f(-e * 13.287712379549449f);   // log2(10000)
        float angle = (float)s * freq;
        pe[s*HH + h] = (h & 1) ? cosf(angle) : sinf(angle);
    }
}

__global__ void zero4_kernel(float* __restrict__ p)
{
    int idx = blockIdx.x*256 + threadIdx.x;
    ((float4*)p)[idx] = make_float4(0.f,0.f,0.f,0.f);
}

// ---------------- small row GEMM + relu into tokens ([s][b] layout) ----------------
// R8 body (serial acc — measured fastest). mode 1: history_s; mode 2: history_a;
// mode 3: single token row 'off'; mode 4: ALL action tokens
__global__ void vecmat_relu(const float* __restrict__ X, int xstride,
                            const float* __restrict__ W, int K,
                            int mode, int off, float* __restrict__ tokens)
{
    int r = blockIdx.x;
    __shared__ float xs[512];
    for (int k = threadIdx.x; k < K; k += 256) xs[k] = X[(size_t)r*xstride + k];
    __syncthreads();
    int drow;
    if      (mode == 1) drow = (2*(r&7))*NB + (r>>3);
    else if (mode == 2) drow = (2*(r&7)+1)*NB + (r>>3);
    else if (mode == 4) drow = (2*THIST + 1 + 2*(r % TACT))*NB + (r / TACT);
    else                drow = off*NB + r;
    int c = blockIdx.y*256 + threadIdx.x;
    float acc = 0.f;
    for (int k = 0; k < K; k++) acc = fmaf(xs[k], W[k*HH + c], acc);
    tokens[drow*HH + c] = fmaxf(acc, 0.f);
}

// ---------------- h = tokens + pe (valid rows; pad rows forced to 0) ----------------
__global__ void addpe_kernel(const float* __restrict__ tokens,
                             const float* __restrict__ pe,
                             float* __restrict__ h,
                             __half* __restrict__ hh, int L)
{
    int i = blockIdx.x*256 + threadIdx.x;
    int srow = i >> 15;                       // s index ([s][b] layout)
    float v = 0.f;
    if (srow < L) v = tokens[i] + pe[srow*HH + (i & 1023)];
    h[i] = v;
    hh[i] = __float2half(v);
}

// ---------------- attention (one block per (b, head)), [s][b] layout ----------------
__global__ void attn_kernel(int L, const float* __restrict__ Q,
                            const float* __restrict__ K,
                            const float* __restrict__ V,
                            __half* __restrict__ ctxh)
{
    __shared__ float Qs[32][64];
    __shared__ float KsT[64][33];
    __shared__ float Vs[32][64];
    __shared__ float P[32][33];
    int tid = threadIdx.x;
    int b = blockIdx.x >> 4, hd = blockIdx.x & 15;
    const float* qb = Q + b*HH + hd*HS;
    const float* kb = K + b*HH + hd*HS;
    const float* vb = V + b*HH + hd*HS;
    #pragma unroll
    for (int t = 0; t < 2; t++) {
        int f = tid + t*256;
        int row = f >> 4, c4 = (f & 15) << 2;
        float4 q4 = *(const float4*)(qb + row*RS + c4);
        *(float4*)&Qs[row][c4] = q4;
        float4 k4 = *(const float4*)(kb + row*RS + c4);
        KsT[c4+0][row] = k4.x; KsT[c4+1][row] = k4.y;
        KsT[c4+2][row] = k4.z; KsT[c4+3][row] = k4.w;
        float4 v4 = *(const float4*)(vb + row*RS + c4);
        *(float4*)&Vs[row][c4] = v4;
    }
    __syncthreads();
    #pragma unroll
    for (int t = 0; t < 4; t++) {
        int p = tid + t*256;
        int qr = p >> 5, kr = p & 31;
        float sc = 0.f;
        #pragma unroll
        for (int d = 0; d < 64; d++) sc = fmaf(Qs[qr][d], KsT[d][kr], sc);
        P[qr][kr] = sc * 0.125f;
    }
    __syncthreads();
    int w = tid >> 5, lane = tid & 31;
    #pragma unroll
    for (int r = 0; r < 4; r++) {
        int qr = w + r*8;
        bool vq = qr < L, vk = lane < L;
        float v = (vq && vk) ? P[qr][lane] : -1e30f;
        float mx = v;
        #pragma unroll
        for (int off = 16; off > 0; off >>= 1)
            mx = fmaxf(mx, __shfl_xor_sync(0xFFFFFFFFu, mx, off));
        float e = (vq && vk) ? expf(v - mx) : 0.f;
        float sm = e;
        #pragma unroll
        for (int off = 16; off > 0; off >>= 1)
            sm += __shfl_xor_sync(0xFFFFFFFFu, sm, off);
        P[qr][lane] = vq ? (e / sm) : 0.f;
    }
    __syncthreads();
    __half* ch = ctxh + b*HH + hd*HS;
    #pragma unroll
    for (int t = 0; t < 8; t++) {
        int e = tid + t*256;
        int qr = e >> 6, d = e & 63;
        float acc = 0.f;
        #pragma unroll
        for (int k = 0; k < 32; k++) acc = fmaf(P[qr][k], Vs[k][d], acc);
        ch[qr*RS + d] = __float2half(acc);
    }
}

// ---------------- LayerNorm(x + y), shuffle reductions, fused fp16 convert ----------------
__global__ void ln_kernel(const float* __restrict__ X, const float* __restrict__ Y,
                          const float* __restrict__ gam, const float* __restrict__ bet,
                          float* __restrict__ out,
                          __half* __restrict__ oh, __half* __restrict__ ph)
{
    int row = blockIdx.x;
    int tid = threadIdx.x, wid = tid >> 5, lane = tid & 31;
    const float* x = X + row*HH;
    const float* y = Y + row*HH;
    float v[4];
    float s = 0.f;
    #pragma unroll
    for (int i = 0; i < 4; i++) { v[i] = x[tid + i*256] + y[tid + i*256]; s += v[i]; }
    #pragma unroll
    for (int off = 16; off > 0; off >>= 1) s += __shfl_xor_sync(0xFFFFFFFFu, s, off);
    __shared__ float red[8], red2[8];
    if (lane == 0) red[wid] = s;
    __syncthreads();
    float tot = 0.f;
    #pragma unroll
    for (int wdx = 0; wdx < 8; wdx++) tot += red[wdx];
    float mean = tot * (1.f/1024.f);
    float q = 0.f;
    #pragma unroll
    for (int i = 0; i < 4; i++) { float d = v[i] - mean; q = fmaf(d, d, q); }
    #pragma unroll
    for (int off = 16; off > 0; off >>= 1) q += __shfl_xor_sync(0xFFFFFFFFu, q, off);
    if (lane == 0) red2[wid] = q;
    __syncthreads();
    float tq = 0.f;
    #pragma unroll
    for (int wdx = 0; wdx < 8; wdx++) tq += red2[wdx];
    float inv = rsqrtf(tq * (1.f/1024.f) + 1e-5f);
    #pragma unroll
    for (int i = 0; i < 4; i++) {
        int c = tid + i*256;
        float o = (v[i] - mean) * inv * gam[c] + bet[c];
        out[row*HH + c] = o;
        __half hv = __float2half(o);
        oh[row*HH + c] = hv;
        if (ph) ph[row*HH + c] = hv;
    }
}

// ---------------- r = sigmoid(hf @ Wr), [s][b] layout ----------------
__global__ void r_kernel(const float* __restrict__ h, const float* __restrict__ Wr,
                         float* __restrict__ out_r, int i)
{
    int b = blockIdx.x;
    int tid = threadIdx.x, wid = tid >> 5, lane = tid & 31;
    float acc = 0.f;
    for (int k = tid; k < SQ*HH; k += 256) {
        int s = k >> 10;
        acc = fmaf(h[s*RS + b*HH + (k & 1023)], Wr[k], acc);
    }
    #pragma unroll
    for (int off = 16; off > 0; off >>= 1) acc += __shfl_xor_sync(0xFFFFFFFFu, acc, off);
    __shared__ float red[8];
    if (lane == 0) red[wid] = acc;
    __syncthreads();
    if (tid == 0) {
        float t = 0.f;
        #pragma unroll
        for (int wdx = 0; wdx < 8; wdx++) t += red[wdx];
        out_r[b*TACT + i] = 1.f / (1.f + expf(-t));
    }
}

// ---------------- s_new partials: split-K 32 (one s-position per y-block) ----------------
__global__ void snew_kernel(const float* __restrict__ h, const float* __restrict__ Wso,
                            float* __restrict__ spart)
{
    __shared__ float As[32][36];
    __shared__ float Bs[32][64];
    int tid = threadIdx.x;
    int n0 = blockIdx.x << 6;
    int k0 = blockIdx.y << 10;
    int sblk = blockIdx.y;
    int col = tid & 63;
    int rg  = tid >> 6;
    int ar = tid >> 3, ac4 = (tid & 7) << 2;
    float acc[8] = {};
    for (int kc = 0; kc < 1024; kc += 32) {
        float4 av = *(const float4*)(h + sblk*RS + ar*HH + kc + ac4);
        As[ar][ac4+0] = av.x; As[ar][ac4+1] = av.y;
        As[ar][ac4+2] = av.z; As[ar][ac4+3] = av.w;
        #pragma unroll
        for (int t = 0; t < 2; t++) {
            int f = tid + t*256;
            int kk = f >> 4, c4 = (f & 15) << 2;
            *(float4*)&Bs[kk][c4] = *(const float4*)(Wso + (size_t)(k0 + kc + kk)*HIN + n0 + c4);
        }
        __syncthreads();
        #pragma unroll 8
        for (int kk = 0; kk < 32; kk++) {
            float bv = Bs[kk][col];
            #pragma unroll
            for (int r8 = 0; r8 < 8; r8++)
                acc[r8] = fmaf(As[rg*8 + r8][kk], bv, acc[r8]);
        }
        __syncthreads();
    }
    #pragma unroll
    for (int r8 = 0; r8 < 8; r8++)
        spart[blockIdx.y*(NB*HIN) + (rg*8 + r8)*HIN + n0 + col] = acc[r8];
}

__global__ void fin_kernel(const float* __restrict__ spart, float* __restrict__ srelu,
                           float* __restrict__ out_s, int i)
{
    int idx = blockIdx.x*256 + threadIdx.x;   // 16384
    float v = 0.f;
    #pragma unroll
    for (int p = 0; p < 32; p++) v += spart[p*(NB*HIN) + idx];
    v = fmaxf(v, 0.f);
    srelu[idx] = v;
    int b = idx >> 9, n = idx & 511;
    out_s[(b*TACT + i)*HIN + n] = v;
}

// ---------------- host orchestration ----------------
extern "C" void kernel_launch(void* const* d_in, const int* in_sizes, int n_in,
                              void* d_out, int out_size)
{
    const float* history_s = (const float*)d_in[0];
    const float* history_a = (const float*)d_in[1];
    const float* s_in      = (const float*)d_in[2];
    const float* a_list    = (const float*)d_in[3];
    const float* Ws        = (const float*)d_in[4];
    const float* Wa        = (const float*)d_in[5];
    const float* Wq        = (const float*)d_in[6];
    const float* Wk        = (const float*)d_in[7];
    const float* Wv        = (const float*)d_in[8];
    const float* Wo        = (const float*)d_in[9];
    const float* Wfc       = (const float*)d_in[10];
    const float* ln1_g     = (const float*)d_in[11];
    const float* ln1_b     = (const float*)d_in[12];
    const float* ln2_g     = (const float*)d_in[13];
    const float* ln2_b     = (const float*)d_in[14];
    const float* Wr        = (const float*)d_in[15];
    const float* Wso       = (const float*)d_in[16];

    float* out_r = (float*)d_out;             // [B, TA]
    float* out_s = out_r + NB*TACT;           // [B, TA, HIN]

    void* p;
    cudaGetSymbolAddress(&p, g_pe);     float* pe     = (float*)p;
    cudaGetSymbolAddress(&p, g_tokens); float* tokens = (float*)p;
    cudaGetSymbolAddress(&p, g_h);      float* h      = (float*)p;
    cudaGetSymbolAddress(&p, g_qbuf);   float* qbuf   = (float*)p;
    cudaGetSymbolAddress(&p, g_kbig);   float* kbig   = (float*)p;
    cudaGetSymbolAddress(&p, g_vbuf);   float* vb     = (float*)p;
    cudaGetSymbolAddress(&p, g_tmp);    float* tmp    = (float*)p;
    cudaGetSymbolAddress(&p, g_spart);  float* spart  = (float*)p;
    cudaGetSymbolAddress(&p, g_srelu);  float* srelu  = (float*)p;
    cudaGetSymbolAddress(&p, g_hh);     __half* hh   = (__half*)p;
    cudaGetSymbolAddress(&p, g_ctxh);   __half* ctxh = (__half*)p;
    cudaGetSymbolAddress(&p, g_phh);    __half* phh  = (__half*)p;
    cudaGetSymbolAddress(&p, g_WhT);    __half* WhT  = (__half*)p;
    cudaGetSymbolAddress(&p, g_WlT);    __half* WlT  = (__half*)p;

    cudaFuncSetAttribute(gemm_tc,   cudaFuncAttributeMaxDynamicSharedMemorySize, GEMM_SMEM);
    cudaFuncSetAttribute(gemm_qkv3, cudaFuncAttributeMaxDynamicSharedMemorySize, GEMM_SMEM);
    cudaFuncSetAttribute(gemm_qk,   cudaFuncAttributeMaxDynamicSharedMemorySize, GEMM_SMEM);

    // side stream + events (fork-join; captured into the graph)
    cudaStream_t s2;
    cudaStreamCreate(&s2);
    cudaEvent_t evLn2[NLAY], evQK[NLAY], evR, evT, evFork;
    for (int j = 0; j < NLAY; j++) {
        cudaEventCreateWithFlags(&evLn2[j], cudaEventDisableTiming);
        cudaEventCreateWithFlags(&evQK[j],  cudaEventDisableTiming);
    }
    cudaEventCreateWithFlags(&evR, cudaEventDisableTiming);
    cudaEventCreateWithFlags(&evT, cudaEventDisableTiming);
    cudaEventCreateWithFlags(&evFork, cudaEventDisableTiming);

    // fork: first op on main records an event; s2 joins the capture by waiting on it.
    pe_kernel<<<SQ, 256>>>(pe);
    cudaEventRecord(evFork, 0);
    cudaStreamWaitEvent(s2, evFork, 0);

    // main: weight conversion.  side: token embeds (independent of W conv).
    wconv_kernel<<<dim3(32, 32, 20), 256>>>(Wq, Wk, Wv, Wo, Wfc, WhT, WlT);

    zero4_kernel<<<TOK_ELEMS/1024, 256, 0, s2>>>(tokens);
    vecmat_relu<<<dim3(NB*THIST, 4), 256, 0, s2>>>(history_s, HIN, Ws, HIN, 1, 0, tokens);
    vecmat_relu<<<dim3(NB*THIST, 4), 256, 0, s2>>>(history_a, AIN, Wa, AIN, 2, 0, tokens);
    vecmat_relu<<<dim3(NB, 4), 256, 0, s2>>>(s_in, HIN, Ws, HIN, 3, 16, tokens);
    vecmat_relu<<<dim3(NB*TACT, 4), 256, 0, s2>>>(a_list, AIN, Wa, AIN, 4, 0, tokens);
    cudaEventRecord(evT, s2);

    for (int i = 0; i < TACT; i++) {
        int posA = 2*THIST + 1 + 2*i;
        int L = posA + 1;
        int M = NB * L;                 // valid rows (prefix), divisible by 64
        int Mt = M >> 6;                // 64-row M-tiles this step
        if (i == 0) cudaStreamWaitEvent(0, evT, 0);   // token embeds ready
        if (i > 0)  cudaStreamWaitEvent(0, evR, 0);   // r of prev step reads h
        addpe_kernel<<<TOK_ELEMS/256, 256>>>(tokens, pe, h, hh, L);

        for (int j = 0; j < NLAY; j++) {
            float* qbj = qbuf + (size_t)j*TOK_ELEMS;
            float* kbj = kbig + (size_t)j*TOK_ELEMS;
            size_t sq = (size_t)(0*4 + j)*WMAT, sk = (size_t)(1*4 + j)*WMAT;
            size_t sv = (size_t)(2*4 + j)*WMAT, so = (size_t)(3*4 + j)*WMAT;
            size_t sf = (size_t)(4*4 + j)*WMAT;

            if (i == 0) {
                gemm_qkv3<<<dim3(8, Mt, 3), 256, GEMM_SMEM>>>(hh, WhT, WlT,
                                                              sq, sk, sv, qbj, kbj, vb, M);
            } else {
                gemm_tc<<<dim3(8, Mt), 256, GEMM_SMEM>>>(hh, WhT + sv, WlT + sv, vb, M);
                cudaStreamWaitEvent(0, evQK[j], 0);     // Q/K precomputed last step
            }
            attn_kernel<<<NB*NHEAD, 256>>>(L, qbj, kbj, vb, ctxh);
            gemm_tc<<<dim3(8, Mt), 256, GEMM_SMEM>>>(ctxh, WhT + so, WlT + so, tmp, M);
            ln_kernel<<<M, 256>>>(h, tmp, ln1_g + j*HH, ln1_b + j*HH, h, hh, (__half*)0);
            gemm_tc<<<dim3(8, Mt), 256, GEMM_SMEM>>>(hh, WhT + sf, WlT + sf, tmp, M);
            ln_kernel<<<M, 256>>>(h, tmp, ln2_g + j*HH, ln2_b + j*HH, h, hh,
                                  phh + (size_t)j*TOK_ELEMS);
            cudaEventRecord(evLn2[j], 0);

            if (i + 1 < TACT) {
                // look-ahead Q/K for next step on the side stream (M+64 rows; pad zero-filled)
                cudaStreamWaitEvent(s2, evLn2[j], 0);
                gemm_qk<<<dim3(8, Mt + 1, 2), 256, GEMM_SMEM, s2>>>(
                    phh + (size_t)j*TOK_ELEMS, WhT, WlT, sq, sk, qbj, kbj, M);
                cudaEventRecord(evQK[j], s2);
            }
        }
        // r on the side stream (off critical path); snew/fin on main
        if (i + 1 >= TACT) cudaStreamWaitEvent(s2, evLn2[NLAY-1], 0);
        r_kernel<<<NB, 256, 0, s2>>>(h, Wr, out_r, i);
        cudaEventRecord(evR, s2);
        snew_kernel<<<dim3(8, 32), 256>>>(h, Wso, spart);
        fin_kernel<<<64, 256>>>(spart, srelu, out_s, i);
        if (i + 1 < TACT)
            vecmat_relu<<<dim3(NB, 4), 256>>>(srelu, HIN, Ws, HIN, 3, posA + 1, tokens);
    }
    cudaStreamWaitEvent(0, evR, 0);   // join side stream before returning

    for (int j = 0; j < NLAY; j++) {
        cudaEventDestroy(evLn2[j]);
        cudaEventDestroy(evQK[j]);
    }
    cudaEventDestroy(evR);
    cudaEventDestroy(evT);
    cudaEventDestroy(evFork);
    cudaStreamDestroy(s2);
}

// round 14
// speedup vs baseline: 1.3863x; 1.1188x over previous
#include <cuda_runtime.h>
#include <cuda_fp16.h>
#include <cstdint>
#include <math.h>

#define NB    32
#define SQ    32
#define HH    1024
#define NHEAD 16
#define HS    64
#define NLAY  4
#define THIST 8
#define TACT  8
#define HIN   512
#define AIN   64
#define RS    (NB*HH)          // 32768: row stride between s-positions

#define TOK_ELEMS (NB*SQ*HH)   // 1048576
#define WMAT      (HH*HH)      // 1048576

// token row layout: row = s*NB + b  (valid rows are prefix [0, 32*L))

// ---------------- scratch (device globals; no allocation) ----------------
__device__ float g_pe[SQ*HH];
__device__ float g_tokens[TOK_ELEMS];
__device__ float g_h[TOK_ELEMS];
__device__ float g_qbuf[NLAY*TOK_ELEMS];   // per-layer Q
__device__ float g_kbig[NLAY*TOK_ELEMS];   // per-layer K
__device__ float g_vbuf[TOK_ELEMS];
__device__ float g_tmp[TOK_ELEMS];
__device__ float g_spart[32*NB*HIN];
__device__ __half g_sreluh[NB*HIN];
__device__ __half g_hh[TOK_ELEMS];                 // fp16 activations
__device__ __half g_ctxh[TOK_ELEMS];
__device__ __half g_phh[NLAY*TOK_ELEMS];
__device__ __half g_WhT[20*WMAT];                  // fp16 weight hi [N,K]
__device__ __half g_WlT[20*WMAT];                  // fp16 weight lo [N,K]
__device__ __half g_WsTh[HH*HIN];                  // Ws^T fp16 hi [1024,512]
__device__ __half g_WsTl[HH*HIN];                  // Ws^T fp16 lo

// ---------------- helpers ----------------
__device__ __forceinline__ uint32_t s2u(const void* p) {
    uint32_t a;
    asm("{ .reg .u64 t; cvta.to.shared.u64 t, %1; cvt.u32.u64 %0, t; }" : "=r"(a) : "l"(p));
    return a;
}

#define LDM4(r, addr) \
    asm volatile("ldmatrix.sync.aligned.m8n8.x4.shared.b16 {%0,%1,%2,%3}, [%4];" \
        : "=r"((r)[0]), "=r"((r)[1]), "=r"((r)[2]), "=r"((r)[3]) : "r"(addr))

#define MMA_F16(d, a, b0v, b1v) \
    asm volatile("mma.sync.aligned.m16n8k16.row.col.f32.f16.f16.f32 " \
        "{%0,%1,%2,%3}, {%4,%5,%6,%7}, {%8,%9}, {%0,%1,%2,%3};" \
        : "+f"((d)[0]), "+f"((d)[1]), "+f"((d)[2]), "+f"((d)[3]) \
        : "r"((a)[0]), "r"((a)[1]), "r"((a)[2]), "r"((a)[3]), "r"(b0v), "r"(b1v))

#define CP_ASYNC16(sa, gp) \
    asm volatile("cp.async.cg.shared.global [%0], [%1], 16;" :: "r"(sa), "l"(gp))
#define CP_ASYNC16Z(sa, gp, sz) \
    asm volatile("cp.async.cg.shared.global [%0], [%1], 16, %2;" :: "r"(sa), "l"(gp), "r"(sz))
#define CP_COMMIT()  asm volatile("cp.async.commit_group;" ::: "memory")
#define CP_WAIT0()   asm volatile("cp.async.wait_group 0;" ::: "memory")
#define CP_WAIT1()   asm volatile("cp.async.wait_group 1;" ::: "memory")
#define CP_WAIT2()   asm volatile("cp.async.wait_group 2;" ::: "memory")

// ---------------- weight transpose + fp16 split: W[K,N] -> WT[N,K] hi/lo ----------------
__global__ void wconv_kernel(const float* __restrict__ Wq, const float* __restrict__ Wk,
                             const float* __restrict__ Wv, const float* __restrict__ Wo,
                             const float* __restrict__ Wfc,
                             __half* __restrict__ WhT, __half* __restrict__ WlT)
{
    int z = blockIdx.z;                 // 0..19 = type*4 + layer
    int type = z >> 2, layer = z & 3;
    const float* bases[5] = {Wq, Wk, Wv, Wo, Wfc};
    const float* W = bases[type] + (size_t)layer * WMAT;
    __shared__ float t[32][33];
    int x0 = blockIdx.x * 32;  // K
    int y0 = blockIdx.y * 32;  // N
    int tr = threadIdx.x >> 5, tc = threadIdx.x & 31;
    #pragma unroll
    for (int u = 0; u < 4; u++) {
        int r = tr + u * 8;
        t[r][tc] = W[(size_t)(x0 + r) * HH + y0 + tc];
    }
    __syncthreads();
    size_t ob = (size_t)z * WMAT;
    #pragma unroll
    for (int u = 0; u < 4; u++) {
        int r = tr + u * 8;
        float v = t[tc][r];
        __half hi = __float2half(v);
        __half lo = __float2half(v - __half2float(hi));
        size_t off = ob + (size_t)(y0 + r) * HH + x0 + tc;
        WhT[off] = hi;
        WlT[off] = lo;
    }
}

// Ws [HIN=512, HH=1024] -> WsT [HH, HIN] fp16 hi/lo
__global__ void wsconv_kernel(const float* __restrict__ Ws,
                              __half* __restrict__ WsTh, __half* __restrict__ WsTl)
{
    __shared__ float t[32][33];
    int x0 = blockIdx.x * 32;  // K (HIN)
    int y0 = blockIdx.y * 32;  // N (HH)
    int tr = threadIdx.x >> 5, tc = threadIdx.x & 31;
    #pragma unroll
    for (int u = 0; u < 4; u++) {
        int r = tr + u * 8;
        t[r][tc] = Ws[(size_t)(x0 + r) * HH + y0 + tc];
    }
    __syncthreads();
    #pragma unroll
    for (int u = 0; u < 4; u++) {
        int r = tr + u * 8;
        float v = t[tc][r];
        __half hi = __float2half(v);
        __half lo = __float2half(v - __half2float(hi));
        size_t off = (size_t)(y0 + r) * HIN + x0 + tc;
        WsTh[off] = hi;
        WsTl[off] = lo;
    }
}

// ---------------- fp16 2-term tensor-core GEMM (mma.sync) ----------------
// C = A x (Bh + Bl)^T, A fp16 [M, K], B [N, K] hi/lo (row stride ldab).
// CTA tile 64(M) x 128(N), K-chunk 64, NST K-stages, 4-buffer pipeline.
// Stage (40960 B): A[0,8K) Bh[8K,24K) Bl[24K,40K)
#define STAGE 40960
#define NBUF  4
#define GEMM_SMEM (NBUF*STAGE)    // 163840

__device__ __forceinline__ void issue_stage(uint32_t sbase, int buf,
    const __half* __restrict__ A,
    const __half* __restrict__ Bh, const __half* __restrict__ Bl,
    int bm, int bn, int k0, int tid, int mvalid, int ldab)
{
    uint32_t st = sbase + buf * STAGE;
    #pragma unroll
    for (int u = 0; u < 10; u++) {
        int id = tid + u * 256;
        if (id < 512) {
            int r = id >> 3, c = id & 7;
            const __half* gp = A + (size_t)(bm + r) * ldab + k0 + c * 8;
            uint32_t sa = st + r * 128 + ((c ^ (r & 7)) << 4);
            uint32_t sz = ((bm + r) < mvalid) ? 16u : 0u;
            CP_ASYNC16Z(sa, gp, sz);
        } else {
            int sec = (id - 512) >> 10;      // 0=Bh 1=Bl
            int t = (id - 512) & 1023;
            int r = t >> 3, c = t & 7;
            const __half* gp = (sec ? Bl : Bh) + (size_t)(bn + r) * ldab + k0 + c * 8;
            uint32_t sa = st + 8192 + sec * 16384 + r * 128 + ((c ^ (r & 7)) << 4);
            CP_ASYNC16(sa, gp);
        }
    }
    CP_COMMIT();
}

template <int NST>
__device__ __forceinline__ void gemm_core(
    const __half* __restrict__ A,
    const __half* __restrict__ Bh, const __half* __restrict__ Bl,
    float* __restrict__ C, int mvalid, int ldab, int ldc, int mstore, int dorelu)
{
    extern __shared__ char smem[];
    uint32_t sbase = s2u(smem);
    int tid = threadIdx.x, wid = tid >> 5, lane = tid & 31;
    int bm = blockIdx.y << 6, bn = blockIdx.x << 7;
    int warpM = (wid >> 2) << 5;
    int warpN = (wid & 3) << 5;

    issue_stage(sbase, 0, A, Bh, Bl, bm, bn, 0,   tid, mvalid, ldab);
    issue_stage(sbase, 1, A, Bh, Bl, bm, bn, 64,  tid, mvalid, ldab);
    issue_stage(sbase, 2, A, Bh, Bl, bm, bn, 128, tid, mvalid, ldab);

    float acc[2][4][4] = {};

    #pragma unroll
    for (int s = 0; s < NST; s++) {
        int rem = NST - 1 - s;
        if (rem >= 2)      { CP_WAIT2(); }
        else if (rem == 1) { CP_WAIT1(); }
        else               { CP_WAIT0(); }
        __syncthreads();
        if (s + 3 < NST)
            issue_stage(sbase, (s + 3) & 3, A, Bh, Bl, bm, bn, (s + 3) << 6, tid, mvalid, ldab);
        uint32_t st = sbase + (s & 3) * STAGE;
        #pragma unroll
        for (int kk = 0; kk < 4; kk++) {
            uint32_t ah[2][4];
            #pragma unroll
            for (int mt = 0; mt < 2; mt++) {
                int r = warpM + mt * 16 + (lane & 15);
                int ch = kk * 2 + (lane >> 4);
                uint32_t ad = st + r * 128 + ((ch ^ (r & 7)) << 4);
                LDM4(ah[mt], ad);
            }
            uint32_t bh[2][4], bl[2][4];
            #pragma unroll
            for (int nt = 0; nt < 2; nt++) {
                int r = warpN + nt * 16 + (lane & 7) + ((lane >> 4) << 3);
                int ch = kk * 2 + ((lane >> 3) & 1);
                uint32_t bd = st + 8192 + r * 128 + ((ch ^ (r & 7)) << 4);
                LDM4(bh[nt], bd);
                LDM4(bl[nt], bd + 16384);
            }
            #pragma unroll
            for (int mt = 0; mt < 2; mt++) {
                #pragma unroll
                for (int j = 0; j < 4; j++) {
                    uint32_t b0 = bh[j >> 1][(j & 1) * 2], b1 = bh[j >> 1][(j & 1) * 2 + 1];
                    uint32_t c0 = bl[j >> 1][(j & 1) * 2], c1 = bl[j >> 1][(j & 1) * 2 + 1];
                    MMA_F16(acc[mt][j], ah[mt], b0, b1);
                    MMA_F16(acc[mt][j], ah[mt], c0, c1);
                }
            }
        }
    }

    #pragma unroll
    for (int mt = 0; mt < 2; mt++) {
        int row = bm + warpM + mt * 16 + (lane >> 2);
        #pragma unroll
        for (int j = 0; j < 4; j++) {
            int col = bn + warpN + j * 8 + ((lane & 3) << 1);
            float v0 = acc[mt][j][0], v1 = acc[mt][j][1];
            float v2 = acc[mt][j][2], v3 = acc[mt][j][3];
            if (dorelu) {
                v0 = fmaxf(v0, 0.f); v1 = fmaxf(v1, 0.f);
                v2 = fmaxf(v2, 0.f); v3 = fmaxf(v3, 0.f);
            }
            if (row < mstore)
                *(float2*)&C[(size_t)row * ldc + col] = make_float2(v0, v1);
            if (row + 8 < mstore)
                *(float2*)&C[(size_t)(row + 8) * ldc + col] = make_float2(v2, v3);
        }
    }
}

__global__ void __launch_bounds__(256, 1) gemm_tc(
    const __half* __restrict__ A,
    const __half* __restrict__ Bh, const __half* __restrict__ Bl,
    float* __restrict__ C, int mvalid)
{
    gemm_core<16>(A, Bh, Bl, C, mvalid, HH, HH, 1 << 30, 0);
}

// step-0 QKV: all operands from current hh
__global__ void __launch_bounds__(256, 1) gemm_qkv3(
    const __half* __restrict__ hh,
    const __half* __restrict__ WhT, const __half* __restrict__ WlT,
    size_t sq, size_t sk, size_t sv,
    float* __restrict__ Q, float* __restrict__ K, float* __restrict__ V, int mvalid)
{
    int z = blockIdx.z;
    size_t off = (z == 0) ? sq : (z == 1) ? sk : sv;
    float* C = (z == 0) ? Q : (z == 1) ? K : V;
    gemm_core<16>(hh, WhT + off, WlT + off, C, mvalid, HH, HH, 1 << 30, 0);
}

// look-ahead Q,K for next step from prev_h[j]
__global__ void __launch_bounds__(256, 1) gemm_qk(
    const __half* __restrict__ ph,
    const __half* __restrict__ WhT, const __half* __restrict__ WlT,
    size_t sq, size_t sk,
    float* __restrict__ Q, float* __restrict__ K, int mvalid)
{
    int z = blockIdx.z;
    size_t off = (z == 0) ? sq : sk;
    float* C = (z == 0) ? Q : K;
    gemm_core<16>(ph, WhT + off, WlT + off, C, mvalid, HH, HH, 1 << 30, 0);
}

// state-token embed: tokens[rowbase+0..31] = relu(sreluh @ WsT^T), K=512
__global__ void __launch_bounds__(256, 1) gemm_tok(
    const __half* __restrict__ sreluh,
    const __half* __restrict__ WsTh, const __half* __restrict__ WsTl,
    float* __restrict__ Cdst)
{
    gemm_core<8>(sreluh, WsTh, WsTl, Cdst, NB, HIN, HH, NB, 1);
}

// ---------------- positional encoding ----------------
__global__ void pe_kernel(float* __restrict__ pe)
{
    int s = blockIdx.x;
    for (int h = threadIdx.x; h < HH; h += 256) {
        float e = (float)(2 * (h / 2)) * (1.0f / HH);
        float freq = exp2f(-e * 13.287712379549449f);   // log2(10000)
        float angle = (float)s * freq;
        pe[s*HH + h] = (h & 1) ? cosf(angle) : sinf(angle);
    }
}

__global__ void zero4_kernel(float* __restrict__ p)
{
    int idx = blockIdx.x*256 + threadIdx.x;
    ((float4*)p)[idx] = make_float4(0.f,0.f,0.f,0.f);
}

// ---------------- small row GEMM + relu into tokens ([s][b] layout) ----------------
// mode 1: history_s; mode 2: history_a; mode 3: single token row 'off';
// mode 4: ALL action tokens
__global__ void vecmat_relu(const float* __restrict__ X, int xstride,
                            const float* __restrict__ W, int K,
                            int mode, int off, float* __restrict__ tokens)
{
    int r = blockIdx.x;
    __shared__ float xs[512];
    for (int k = threadIdx.x; k < K; k += 256) xs[k] = X[(size_t)r*xstride + k];
    __syncthreads();
    int drow;
    if      (mode == 1) drow = (2*(r&7))*NB + (r>>3);
    else if (mode == 2) drow = (2*(r&7)+1)*NB + (r>>3);
    else if (mode == 4) drow = (2*THIST + 1 + 2*(r % TACT))*NB + (r / TACT);
    else                drow = off*NB + r;
    int c = blockIdx.y*256 + threadIdx.x;
    float acc = 0.f;
    for (int k = 0; k < K; k++) acc = fmaf(xs[k], W[k*HH + c], acc);
    tokens[drow*HH + c] = fmaxf(acc, 0.f);
}

// ---------------- h = tokens + pe (valid rows; pad rows forced to 0) ----------------
__global__ void addpe_kernel(const float* __restrict__ tokens,
                             const float* __restrict__ pe,
                             float* __restrict__ h,
                             __half* __restrict__ hh, int L)
{
    int i = blockIdx.x*256 + threadIdx.x;
    int srow = i >> 15;                       // s index ([s][b] layout)
    float v = 0.f;
    if (srow < L) v = tokens[i] + pe[srow*HH + (i & 1023)];
    h[i] = v;
    hh[i] = __float2half(v);
}

// ---------------- attention (one block per (b, head)), [s][b] layout ----------------
__global__ void attn_kernel(int L, const float* __restrict__ Q,
                            const float* __restrict__ K,
                            const float* __restrict__ V,
                            __half* __restrict__ ctxh)
{
    __shared__ float Qs[32][64];
    __shared__ float KsT[64][33];
    __shared__ float Vs[32][64];
    __shared__ float P[32][33];
    int tid = threadIdx.x;
    int b = blockIdx.x >> 4, hd = blockIdx.x & 15;
    const float* qb = Q + b*HH + hd*HS;
    const float* kb = K + b*HH + hd*HS;
    const float* vb = V + b*HH + hd*HS;
    #pragma unroll
    for (int t = 0; t < 2; t++) {
        int f = tid + t*256;
        int row = f >> 4, c4 = (f & 15) << 2;
        float4 q4 = *(const float4*)(qb + row*RS + c4);
        *(float4*)&Qs[row][c4] = q4;
        float4 k4 = *(const float4*)(kb + row*RS + c4);
        KsT[c4+0][row] = k4.x; KsT[c4+1][row] = k4.y;
        KsT[c4+2][row] = k4.z; KsT[c4+3][row] = k4.w;
        float4 v4 = *(const float4*)(vb + row*RS + c4);
        *(float4*)&Vs[row][c4] = v4;
    }
    __syncthreads();
    #pragma unroll
    for (int t = 0; t < 4; t++) {
        int p = tid + t*256;
        int qr = p >> 5, kr = p & 31;
        float sc = 0.f;
        #pragma unroll
        for (int d = 0; d < 64; d++) sc = fmaf(Qs[qr][d], KsT[d][kr], sc);
        P[qr][kr] = sc * 0.125f;
    }
    __syncthreads();
    int w = tid >> 5, lane = tid & 31;
    #pragma unroll
    for (int r = 0; r < 4; r++) {
        int qr = w + r*8;
        bool vq = qr < L, vk = lane < L;
        float v = (vq && vk) ? P[qr][lane] : -1e30f;
        float mx = v;
        #pragma unroll
        for (int off = 16; off > 0; off >>= 1)
            mx = fmaxf(mx, __shfl_xor_sync(0xFFFFFFFFu, mx, off));
        float e = (vq && vk) ? expf(v - mx) : 0.f;
        float sm = e;
        #pragma unroll
        for (int off = 16; off > 0; off >>= 1)
            sm += __shfl_xor_sync(0xFFFFFFFFu, sm, off);
        P[qr][lane] = vq ? (e / sm) : 0.f;
    }
    __syncthreads();
    __half* ch = ctxh + b*HH + hd*HS;
    #pragma unroll
    for (int t = 0; t < 8; t++) {
        int e = tid + t*256;
        int qr = e >> 6, d = e & 63;
        float acc = 0.f;
        #pragma unroll
        for (int k = 0; k < 32; k++) acc = fmaf(P[qr][k], Vs[k][d], acc);
        ch[qr*RS + d] = __float2half(acc);
    }
}

// ---------------- LayerNorm(x + y), shuffle reductions, fused fp16 convert ----------------
__global__ void ln_kernel(const float* __restrict__ X, const float* __restrict__ Y,
                          const float* __restrict__ gam, const float* __restrict__ bet,
                          float* __restrict__ out,
                          __half* __restrict__ oh, __half* __restrict__ ph)
{
    int row = blockIdx.x;
    int tid = threadIdx.x, wid = tid >> 5, lane = tid & 31;
    const float* x = X + row*HH;
    const float* y = Y + row*HH;
    float v[4];
    float s = 0.f;
    #pragma unroll
    for (int i = 0; i < 4; i++) { v[i] = x[tid + i*256] + y[tid + i*256]; s += v[i]; }
    #pragma unroll
    for (int off = 16; off > 0; off >>= 1) s += __shfl_xor_sync(0xFFFFFFFFu, s, off);
    __shared__ float red[8], red2[8];
    if (lane == 0) red[wid] = s;
    __syncthreads();
    float tot = 0.f;
    #pragma unroll
    for (int wdx = 0; wdx < 8; wdx++) tot += red[wdx];
    float mean = tot * (1.f/1024.f);
    float q = 0.f;
    #pragma unroll
    for (int i = 0; i < 4; i++) { float d = v[i] - mean; q = fmaf(d, d, q); }
    #pragma unroll
    for (int off = 16; off > 0; off >>= 1) q += __shfl_xor_sync(0xFFFFFFFFu, q, off);
    if (lane == 0) red2[wid] = q;
    __syncthreads();
    float tq = 0.f;
    #pragma unroll
    for (int wdx = 0; wdx < 8; wdx++) tq += red2[wdx];
    float inv = rsqrtf(tq * (1.f/1024.f) + 1e-5f);
    #pragma unroll
    for (int i = 0; i < 4; i++) {
        int c = tid + i*256;
        float o = (v[i] - mean) * inv * gam[c] + bet[c];
        out[row*HH + c] = o;
        __half hv = __float2half(o);
        oh[row*HH + c] = hv;
        if (ph) ph[row*HH + c] = hv;
    }
}

// ---------------- r = sigmoid(hf @ Wr), [s][b] layout ----------------
__global__ void r_kernel(const float* __restrict__ h, const float* __restrict__ Wr,
                         float* __restrict__ out_r, int i)
{
    int b = blockIdx.x;
    int tid = threadIdx.x, wid = tid >> 5, lane = tid & 31;
    float acc = 0.f;
    for (int k = tid; k < SQ*HH; k += 256) {
        int s = k >> 10;
        acc = fmaf(h[s*RS + b*HH + (k & 1023)], Wr[k], acc);
    }
    #pragma unroll
    for (int off = 16; off > 0; off >>= 1) acc += __shfl_xor_sync(0xFFFFFFFFu, acc, off);
    __shared__ float red[8];
    if (lane == 0) red[wid] = acc;
    __syncthreads();
    if (tid == 0) {
        float t = 0.f;
        #pragma unroll
        for (int wdx = 0; wdx < 8; wdx++) t += red[wdx];
        out_r[b*TACT + i] = 1.f / (1.f + expf(-t));
    }
}

// ---------------- s_new partials: split-K 32 (one s-position per y-block) ----------------
__global__ void snew_kernel(const float* __restrict__ h, const float* __restrict__ Wso,
                            float* __restrict__ spart)
{
    __shared__ float As[32][36];
    __shared__ float Bs[32][64];
    int tid = threadIdx.x;
    int n0 = blockIdx.x << 6;
    int k0 = blockIdx.y << 10;
    int sblk = blockIdx.y;
    int col = tid & 63;
    int rg  = tid >> 6;
    int ar = tid >> 3, ac4 = (tid & 7) << 2;
    float acc[8] = {};
    for (int kc = 0; kc < 1024; kc += 32) {
        float4 av = *(const float4*)(h + sblk*RS + ar*HH + kc + ac4);
        As[ar][ac4+0] = av.x; As[ar][ac4+1] = av.y;
        As[ar][ac4+2] = av.z; As[ar][ac4+3] = av.w;
        #pragma unroll
        for (int t = 0; t < 2; t++) {
            int f = tid + t*256;
            int kk = f >> 4, c4 = (f & 15) << 2;
            *(float4*)&Bs[kk][c4] = *(const float4*)(Wso + (size_t)(k0 + kc + kk)*HIN + n0 + c4);
        }
        __syncthreads();
        #pragma unroll 8
        for (int kk = 0; kk < 32; kk++) {
            float bv = Bs[kk][col];
            #pragma unroll
            for (int r8 = 0; r8 < 8; r8++)
                acc[r8] = fmaf(As[rg*8 + r8][kk], bv, acc[r8]);
        }
        __syncthreads();
    }
    #pragma unroll
    for (int r8 = 0; r8 < 8; r8++)
        spart[blockIdx.y*(NB*HIN) + (rg*8 + r8)*HIN + n0 + col] = acc[r8];
}

__global__ void fin_kernel(const float* __restrict__ spart, __half* __restrict__ sreluh,
                           float* __restrict__ out_s, int i)
{
    int idx = blockIdx.x*256 + threadIdx.x;   // 16384
    float v = 0.f;
    #pragma unroll
    for (int p = 0; p < 32; p++) v += spart[p*(NB*HIN) + idx];
    v = fmaxf(v, 0.f);
    sreluh[idx] = __float2half(v);
    int b = idx >> 9, n = idx & 511;
    out_s[(b*TACT + i)*HIN + n] = v;
}

// ---------------- host orchestration ----------------
extern "C" void kernel_launch(void* const* d_in, const int* in_sizes, int n_in,
                              void* d_out, int out_size)
{
    const float* history_s = (const float*)d_in[0];
    const float* history_a = (const float*)d_in[1];
    const float* s_in      = (const float*)d_in[2];
    const float* a_list    = (const float*)d_in[3];
    const float* Ws        = (const float*)d_in[4];
    const float* Wa        = (const float*)d_in[5];
    const float* Wq        = (const float*)d_in[6];
    const float* Wk        = (const float*)d_in[7];
    const float* Wv        = (const float*)d_in[8];
    const float* Wo        = (const float*)d_in[9];
    const float* Wfc       = (const float*)d_in[10];
    const float* ln1_g     = (const float*)d_in[11];
    const float* ln1_b     = (const float*)d_in[12];
    const float* ln2_g     = (const float*)d_in[13];
    const float* ln2_b     = (const float*)d_in[14];
    const float* Wr        = (const float*)d_in[15];
    const float* Wso       = (const float*)d_in[16];

    float* out_r = (float*)d_out;             // [B, TA]
    float* out_s = out_r + NB*TACT;           // [B, TA, HIN]

    void* p;
    cudaGetSymbolAddress(&p, g_pe);     float* pe     = (float*)p;
    cudaGetSymbolAddress(&p, g_tokens); float* tokens = (float*)p;
    cudaGetSymbolAddress(&p, g_h);      float* h      = (float*)p;
    cudaGetSymbolAddress(&p, g_qbuf);   float* qbuf   = (float*)p;
    cudaGetSymbolAddress(&p, g_kbig);   float* kbig   = (float*)p;
    cudaGetSymbolAddress(&p, g_vbuf);   float* vb     = (float*)p;
    cudaGetSymbolAddress(&p, g_tmp);    float* tmp    = (float*)p;
    cudaGetSymbolAddress(&p, g_spart);  float* spart  = (float*)p;
    cudaGetSymbolAddress(&p, g_sreluh); __half* sreluh = (__half*)p;
    cudaGetSymbolAddress(&p, g_hh);     __half* hh   = (__half*)p;
    cudaGetSymbolAddress(&p, g_ctxh);   __half* ctxh = (__half*)p;
    cudaGetSymbolAddress(&p, g_phh);    __half* phh  = (__half*)p;
    cudaGetSymbolAddress(&p, g_WhT);    __half* WhT  = (__half*)p;
    cudaGetSymbolAddress(&p, g_WlT);    __half* WlT  = (__half*)p;
    cudaGetSymbolAddress(&p, g_WsTh);   __half* WsTh = (__half*)p;
    cudaGetSymbolAddress(&p, g_WsTl);   __half* WsTl = (__half*)p;

    cudaFuncSetAttribute(gemm_tc,   cudaFuncAttributeMaxDynamicSharedMemorySize, GEMM_SMEM);
    cudaFuncSetAttribute(gemm_qkv3, cudaFuncAttributeMaxDynamicSharedMemorySize, GEMM_SMEM);
    cudaFuncSetAttribute(gemm_qk,   cudaFuncAttributeMaxDynamicSharedMemorySize, GEMM_SMEM);
    cudaFuncSetAttribute(gemm_tok,  cudaFuncAttributeMaxDynamicSharedMemorySize, GEMM_SMEM);

    // side stream + events (fork-join; captured into the graph)
    cudaStream_t s2;
    cudaStreamCreate(&s2);
    cudaEvent_t evLn2[NLAY], evQK[NLAY], evR, evT, evFork;
    for (int j = 0; j < NLAY; j++) {
        cudaEventCreateWithFlags(&evLn2[j], cudaEventDisableTiming);
        cudaEventCreateWithFlags(&evQK[j],  cudaEventDisableTiming);
    }
    cudaEventCreateWithFlags(&evR, cudaEventDisableTiming);
    cudaEventCreateWithFlags(&evT, cudaEventDisableTiming);
    cudaEventCreateWithFlags(&evFork, cudaEventDisableTiming);

    // fork: first op on main records an event; s2 joins the capture by waiting on it.
    pe_kernel<<<SQ, 256>>>(pe);
    cudaEventRecord(evFork, 0);
    cudaStreamWaitEvent(s2, evFork, 0);

    // main: weight conversions.  side: token embeds (independent of W conv).
    wconv_kernel<<<dim3(32, 32, 20), 256>>>(Wq, Wk, Wv, Wo, Wfc, WhT, WlT);
    wsconv_kernel<<<dim3(16, 32), 256>>>(Ws, WsTh, WsTl);

    zero4_kernel<<<TOK_ELEMS/1024, 256, 0, s2>>>(tokens);
    vecmat_relu<<<dim3(NB*THIST, 4), 256, 0, s2>>>(history_s, HIN, Ws, HIN, 1, 0, tokens);
    vecmat_relu<<<dim3(NB*THIST, 4), 256, 0, s2>>>(history_a, AIN, Wa, AIN, 2, 0, tokens);
    vecmat_relu<<<dim3(NB, 4), 256, 0, s2>>>(s_in, HIN, Ws, HIN, 3, 16, tokens);
    vecmat_relu<<<dim3(NB*TACT, 4), 256, 0, s2>>>(a_list, AIN, Wa, AIN, 4, 0, tokens);
    cudaEventRecord(evT, s2);

    for (int i = 0; i < TACT; i++) {
        int posA = 2*THIST + 1 + 2*i;
        int L = posA + 1;
        int M = NB * L;                 // valid rows (prefix), divisible by 64
        int Mt = M >> 6;                // 64-row M-tiles this step
        if (i == 0) cudaStreamWaitEvent(0, evT, 0);   // token embeds ready
        if (i > 0)  cudaStreamWaitEvent(0, evR, 0);   // r of prev step reads h
        addpe_kernel<<<TOK_ELEMS/256, 256>>>(tokens, pe, h, hh, L);

        for (int j = 0; j < NLAY; j++) {
            float* qbj = qbuf + (size_t)j*TOK_ELEMS;
            float* kbj = kbig + (size_t)j*TOK_ELEMS;
            size_t sq = (size_t)(0*4 + j)*WMAT, sk = (size_t)(1*4 + j)*WMAT;
            size_t sv = (size_t)(2*4 + j)*WMAT, so = (size_t)(3*4 + j)*WMAT;
            size_t sf = (size_t)(4*4 + j)*WMAT;

            if (i == 0) {
                gemm_qkv3<<<dim3(8, Mt, 3), 256, GEMM_SMEM>>>(hh, WhT, WlT,
                                                              sq, sk, sv, qbj, kbj, vb, M);
            } else {
                gemm_tc<<<dim3(8, Mt), 256, GEMM_SMEM>>>(hh, WhT + sv, WlT + sv, vb, M);
                cudaStreamWaitEvent(0, evQK[j], 0);     // Q/K precomputed last step
            }
            attn_kernel<<<NB*NHEAD, 256>>>(L, qbj, kbj, vb, ctxh);
            gemm_tc<<<dim3(8, Mt), 256, GEMM_SMEM>>>(ctxh, WhT + so, WlT + so, tmp, M);
            ln_kernel<<<M, 256>>>(h, tmp, ln1_g + j*HH, ln1_b + j*HH, h, hh, (__half*)0);
            gemm_tc<<<dim3(8, Mt), 256, GEMM_SMEM>>>(hh, WhT + sf, WlT + sf, tmp, M);
            ln_kernel<<<M, 256>>>(h, tmp, ln2_g + j*HH, ln2_b + j*HH, h, hh,
                                  phh + (size_t)j*TOK_ELEMS);
            cudaEventRecord(evLn2[j], 0);

            if (i + 1 < TACT) {
                // look-ahead Q/K for next step on the side stream (M+64 rows; pad zero-filled)
                cudaStreamWaitEvent(s2, evLn2[j], 0);
                gemm_qk<<<dim3(8, Mt + 1, 2), 256, GEMM_SMEM, s2>>>(
                    phh + (size_t)j*TOK_ELEMS, WhT, WlT, sq, sk, qbj, kbj, M);
                cudaEventRecord(evQK[j], s2);
            }
        }
        // r on the side stream (off critical path); snew/fin on main
        if (i + 1 >= TACT) cudaStreamWaitEvent(s2, evLn2[NLAY-1], 0);
        r_kernel<<<NB, 256, 0, s2>>>(h, Wr, out_r, i);
        cudaEventRecord(evR, s2);
        snew_kernel<<<dim3(8, 32), 256>>>(h, Wso, spart);
        fin_kernel<<<64, 256>>>(spart, sreluh, out_s, i);
        if (i + 1 < TACT)
            gemm_tok<<<dim3(8, 1), 256, GEMM_SMEM>>>(sreluh, WsTh, WsTl,
                                                     tokens + (size_t)(posA + 1)*NB*HH);
    }
    cudaStreamWaitEvent(0, evR, 0);   // join side stream before returning

    for (int j = 0; j < NLAY; j++) {
        cudaEventDestroy(evLn2[j]);
        cudaEventDestroy(evQK[j]);
    }
    cudaEventDestroy(evR);
    cudaEventDestroy(evT);
    cudaEventDestroy(evFork);
    cudaStreamDestroy(s2);
}

// round 16
// speedup vs baseline: 1.7861x; 1.2884x over previous
#include <cuda_runtime.h>
#include <cuda_fp16.h>
#include <cstdint>
#include <math.h>

#define NB    32
#define SQ    32
#define HH    1024
#define NHEAD 16
#define HS    64
#define NLAY  4
#define THIST 8
#define TACT  8
#define HIN   512
#define AIN   64
#define RS    (NB*HH)          // 32768: row stride between s-positions

#define TOK_ELEMS (NB*SQ*HH)   // 1048576
#define WMAT      (HH*HH)      // 1048576

// token row layout: row = s*NB + b  (valid rows are prefix [0, 32*L))

// ---------------- scratch (device globals; no allocation) ----------------
__device__ float g_pe[SQ*HH];
__device__ float g_tokens[TOK_ELEMS];
__device__ float g_h[TOK_ELEMS];
__device__ float g_qbuf[NLAY*TOK_ELEMS];   // per-layer Q
__device__ float g_kbig[NLAY*TOK_ELEMS];   // per-layer K
__device__ float g_vbuf[TOK_ELEMS];
__device__ float g_tmp[TOK_ELEMS];
__device__ float g_spart[32*NB*HIN];
__device__ __half g_sreluh[NB*HIN];
__device__ __half g_hh[TOK_ELEMS];                 // fp16 activations
__device__ __half g_ctxh[TOK_ELEMS];
__device__ __half g_phh[NLAY*TOK_ELEMS];
__device__ __half g_WhT[20*WMAT];                  // fp16 weights [N,K]
__device__ __half g_WsTh[HH*HIN];                  // Ws^T fp16 [1024,512]

// ---------------- helpers ----------------
__device__ __forceinline__ uint32_t s2u(const void* p) {
    uint32_t a;
    asm("{ .reg .u64 t; cvta.to.shared.u64 t, %1; cvt.u32.u64 %0, t; }" : "=r"(a) : "l"(p));
    return a;
}

#define LDM4(r, addr) \
    asm volatile("ldmatrix.sync.aligned.m8n8.x4.shared.b16 {%0,%1,%2,%3}, [%4];" \
        : "=r"((r)[0]), "=r"((r)[1]), "=r"((r)[2]), "=r"((r)[3]) : "r"(addr))

#define MMA_F16(d, a, b0v, b1v) \
    asm volatile("mma.sync.aligned.m16n8k16.row.col.f32.f16.f16.f32 " \
        "{%0,%1,%2,%3}, {%4,%5,%6,%7}, {%8,%9}, {%0,%1,%2,%3};" \
        : "+f"((d)[0]), "+f"((d)[1]), "+f"((d)[2]), "+f"((d)[3]) \
        : "r"((a)[0]), "r"((a)[1]), "r"((a)[2]), "r"((a)[3]), "r"(b0v), "r"(b1v))

#define CP_ASYNC16(sa, gp) \
    asm volatile("cp.async.cg.shared.global [%0], [%1], 16;" :: "r"(sa), "l"(gp))
#define CP_ASYNC16Z(sa, gp, sz) \
    asm volatile("cp.async.cg.shared.global [%0], [%1], 16, %2;" :: "r"(sa), "l"(gp), "r"(sz))
#define CP_COMMIT()  asm volatile("cp.async.commit_group;" ::: "memory")
#define CP_WAIT0()   asm volatile("cp.async.wait_group 0;" ::: "memory")
#define CP_WAIT1()   asm volatile("cp.async.wait_group 1;" ::: "memory")
#define CP_WAIT2()   asm volatile("cp.async.wait_group 2;" ::: "memory")

// ---------------- weight transpose + fp16: W[K,N] -> WT[N,K] ----------------
__global__ void wconv_kernel(const float* __restrict__ Wq, const float* __restrict__ Wk,
                             const float* __restrict__ Wv, const float* __restrict__ Wo,
                             const float* __restrict__ Wfc,
                             __half* __restrict__ WhT)
{
    int z = blockIdx.z;                 // 0..19 = type*4 + layer
    int type = z >> 2, layer = z & 3;
    const float* bases[5] = {Wq, Wk, Wv, Wo, Wfc};
    const float* W = bases[type] + (size_t)layer * WMAT;
    __shared__ float t[32][33];
    int x0 = blockIdx.x * 32;  // K
    int y0 = blockIdx.y * 32;  // N
    int tr = threadIdx.x >> 5, tc = threadIdx.x & 31;
    #pragma unroll
    for (int u = 0; u < 4; u++) {
        int r = tr + u * 8;
        t[r][tc] = W[(size_t)(x0 + r) * HH + y0 + tc];
    }
    __syncthreads();
    size_t ob = (size_t)z * WMAT;
    #pragma unroll
    for (int u = 0; u < 4; u++) {
        int r = tr + u * 8;
        WhT[ob + (size_t)(y0 + r) * HH + x0 + tc] = __float2half(t[tc][r]);
    }
}

// Ws [HIN=512, HH=1024] -> WsT [HH, HIN] fp16
__global__ void wsconv_kernel(const float* __restrict__ Ws, __half* __restrict__ WsTh)
{
    __shared__ float t[32][33];
    int x0 = blockIdx.x * 32;  // K (HIN)
    int y0 = blockIdx.y * 32;  // N (HH)
    int tr = threadIdx.x >> 5, tc = threadIdx.x & 31;
    #pragma unroll
    for (int u = 0; u < 4; u++) {
        int r = tr + u * 8;
        t[r][tc] = Ws[(size_t)(x0 + r) * HH + y0 + tc];
    }
    __syncthreads();
    #pragma unroll
    for (int u = 0; u < 4; u++) {
        int r = tr + u * 8;
        WsTh[(size_t)(y0 + r) * HIN + x0 + tc] = __float2half(t[tc][r]);
    }
}

// ---------------- fp16 tensor-core GEMM (mma.sync), 1-term ----------------
// C = A x B^T, A fp16 [M, K], B [N, K] (row stride ldab).
// CTA tile 64(M) x 128(N), K-chunk 64, NST K-stages, 4-buffer pipeline, 2 CTAs/SM.
// Stage (24576 B): A[0,8K) B[8K,24K)
#define STAGE 24576
#define NBUF  4
#define GEMM_SMEM (NBUF*STAGE)    // 98304

__device__ __forceinline__ void issue_stage(uint32_t sbase, int buf,
    const __half* __restrict__ A, const __half* __restrict__ B,
    int bm, int bn, int k0, int tid, int mvalid, int ldab)
{
    uint32_t st = sbase + buf * STAGE;
    #pragma unroll
    for (int u = 0; u < 6; u++) {
        int id = tid + u * 256;             // 0..1535
        if (id < 512) {
            int r = id >> 3, c = id & 7;
            const __half* gp = A + (size_t)(bm + r) * ldab + k0 + c * 8;
            uint32_t sa = st + r * 128 + ((c ^ (r & 7)) << 4);
            uint32_t sz = ((bm + r) < mvalid) ? 16u : 0u;
            CP_ASYNC16Z(sa, gp, sz);
        } else {
            int t = id - 512;               // 0..1023
            int r = t >> 3, c = t & 7;
            const __half* gp = B + (size_t)(bn + r) * ldab + k0 + c * 8;
            uint32_t sa = st + 8192 + r * 128 + ((c ^ (r & 7)) << 4);
            CP_ASYNC16(sa, gp);
        }
    }
    CP_COMMIT();
}

template <int NST>
__device__ __forceinline__ void gemm_core(
    const __half* __restrict__ A, const __half* __restrict__ B,
    float* __restrict__ C, int mvalid, int ldab, int ldc, int mstore, int dorelu)
{
    extern __shared__ char smem[];
    uint32_t sbase = s2u(smem);
    int tid = threadIdx.x, wid = tid >> 5, lane = tid & 31;
    int bm = blockIdx.y << 6, bn = blockIdx.x << 7;
    int warpM = (wid >> 2) << 5;
    int warpN = (wid & 3) << 5;

    issue_stage(sbase, 0, A, B, bm, bn, 0,   tid, mvalid, ldab);
    issue_stage(sbase, 1, A, B, bm, bn, 64,  tid, mvalid, ldab);
    issue_stage(sbase, 2, A, B, bm, bn, 128, tid, mvalid, ldab);

    float acc[2][4][4] = {};

    #pragma unroll
    for (int s = 0; s < NST; s++) {
        int rem = NST - 1 - s;
        if (rem >= 2)      { CP_WAIT2(); }
        else if (rem == 1) { CP_WAIT1(); }
        else               { CP_WAIT0(); }
        __syncthreads();
        if (s + 3 < NST)
            issue_stage(sbase, (s + 3) & 3, A, B, bm, bn, (s + 3) << 6, tid, mvalid, ldab);
        uint32_t st = sbase + (s & 3) * STAGE;
        #pragma unroll
        for (int kk = 0; kk < 4; kk++) {
            uint32_t ah[2][4];
            #pragma unroll
            for (int mt = 0; mt < 2; mt++) {
                int r = warpM + mt * 16 + (lane & 15);
                int ch = kk * 2 + (lane >> 4);
                uint32_t ad = st + r * 128 + ((ch ^ (r & 7)) << 4);
                LDM4(ah[mt], ad);
            }
            uint32_t bh[2][4];
            #pragma unroll
            for (int nt = 0; nt < 2; nt++) {
                int r = warpN + nt * 16 + (lane & 7) + ((lane >> 4) << 3);
                int ch = kk * 2 + ((lane >> 3) & 1);
                uint32_t bd = st + 8192 + r * 128 + ((ch ^ (r & 7)) << 4);
                LDM4(bh[nt], bd);
            }
            #pragma unroll
            for (int mt = 0; mt < 2; mt++) {
                #pragma unroll
                for (int j = 0; j < 4; j++) {
                    uint32_t b0 = bh[j >> 1][(j & 1) * 2], b1 = bh[j >> 1][(j & 1) * 2 + 1];
                    MMA_F16(acc[mt][j], ah[mt], b0, b1);
                }
            }
        }
    }

    #pragma unroll
    for (int mt = 0; mt < 2; mt++) {
        int row = bm + warpM + mt * 16 + (lane >> 2);
        #pragma unroll
        for (int j = 0; j < 4; j++) {
            int col = bn + warpN + j * 8 + ((lane & 3) << 1);
            float v0 = acc[mt][j][0], v1 = acc[mt][j][1];
            float v2 = acc[mt][j][2], v3 = acc[mt][j][3];
            if (dorelu) {
                v0 = fmaxf(v0, 0.f); v1 = fmaxf(v1, 0.f);
                v2 = fmaxf(v2, 0.f); v3 = fmaxf(v3, 0.f);
            }
            if (row < mstore)
                *(float2*)&C[(size_t)row * ldc + col] = make_float2(v0, v1);
            if (row + 8 < mstore)
                *(float2*)&C[(size_t)(row + 8) * ldc + col] = make_float2(v2, v3);
        }
    }
}

__global__ void __launch_bounds__(256, 2) gemm_tc(
    const __half* __restrict__ A, const __half* __restrict__ B,
    float* __restrict__ C, int mvalid)
{
    gemm_core<16>(A, B, C, mvalid, HH, HH, 1 << 30, 0);
}

// step-0 QKV: all operands from current hh
__global__ void __launch_bounds__(256, 2) gemm_qkv3(
    const __half* __restrict__ hh, const __half* __restrict__ WhT,
    size_t sq, size_t sk, size_t sv,
    float* __restrict__ Q, float* __restrict__ K, float* __restrict__ V, int mvalid)
{
    int z = blockIdx.z;
    size_t off = (z == 0) ? sq : (z == 1) ? sk : sv;
    float* C = (z == 0) ? Q : (z == 1) ? K : V;
    gemm_core<16>(hh, WhT + off, C, mvalid, HH, HH, 1 << 30, 0);
}

// look-ahead Q,K for next step from prev_h[j]
__global__ void __launch_bounds__(256, 2) gemm_qk(
    const __half* __restrict__ ph, const __half* __restrict__ WhT,
    size_t sq, size_t sk,
    float* __restrict__ Q, float* __restrict__ K, int mvalid)
{
    int z = blockIdx.z;
    size_t off = (z == 0) ? sq : sk;
    float* C = (z == 0) ? Q : K;
    gemm_core<16>(ph, WhT + off, C, mvalid, HH, HH, 1 << 30, 0);
}

// state-token embed: tokens[rowbase+0..31] = relu(sreluh @ WsT^T), K=512
__global__ void __launch_bounds__(256, 2) gemm_tok(
    const __half* __restrict__ sreluh, const __half* __restrict__ WsTh,
    float* __restrict__ Cdst)
{
    gemm_core<8>(sreluh, WsTh, Cdst, NB, HIN, HH, NB, 1);
}

// ---------------- positional encoding ----------------
__global__ void pe_kernel(float* __restrict__ pe)
{
    int s = blockIdx.x;
    for (int h = threadIdx.x; h < HH; h += 256) {
        float e = (float)(2 * (h / 2)) * (1.0f / HH);
        float freq = exp2f(-e * 13.287712379549449f);   // log2(10000)
        float angle = (float)s * freq;
        pe[s*HH + h] = (h & 1) ? cosf(angle) : sinf(angle);
    }
}

__global__ void zero4_kernel(float* __restrict__ p)
{
    int idx = blockIdx.x*256 + threadIdx.x;
    ((float4*)p)[idx] = make_float4(0.f,0.f,0.f,0.f);
}

// ---------------- small row GEMM + relu into tokens ([s][b] layout) ----------------
// mode 1: history_s; mode 2: history_a; mode 3: single token row 'off';
// mode 4: ALL action tokens
__global__ void vecmat_relu(const float* __restrict__ X, int xstride,
                            const float* __restrict__ W, int K,
                            int mode, int off, float* __restrict__ tokens)
{
    int r = blockIdx.x;
    __shared__ float xs[512];
    for (int k = threadIdx.x; k < K; k += 256) xs[k] = X[(size_t)r*xstride + k];
    __syncthreads();
    int drow;
    if      (mode == 1) drow = (2*(r&7))*NB + (r>>3);
    else if (mode == 2) drow = (2*(r&7)+1)*NB + (r>>3);
    else if (mode == 4) drow = (2*THIST + 1 + 2*(r % TACT))*NB + (r / TACT);
    else                drow = off*NB + r;
    int c = blockIdx.y*256 + threadIdx.x;
    float acc = 0.f;
    for (int k = 0; k < K; k++) acc = fmaf(xs[k], W[k*HH + c], acc);
    tokens[drow*HH + c] = fmaxf(acc, 0.f);
}

// ---------------- h = tokens + pe (valid rows; pad rows forced to 0) ----------------
__global__ void addpe_kernel(const float* __restrict__ tokens,
                             const float* __restrict__ pe,
                             float* __restrict__ h,
                             __half* __restrict__ hh, int L)
{
    int i = blockIdx.x*256 + threadIdx.x;
    int srow = i >> 15;                       // s index ([s][b] layout)
    float v = 0.f;
    if (srow < L) v = tokens[i] + pe[srow*HH + (i & 1023)];
    h[i] = v;
    hh[i] = __float2half(v);
}

// ---------------- attention (one block per (b, head)), [s][b] layout ----------------
__global__ void attn_kernel(int L, const float* __restrict__ Q,
                            const float* __restrict__ K,
                            const float* __restrict__ V,
                            __half* __restrict__ ctxh)
{
    __shared__ float Qs[32][64];
    __shared__ float KsT[64][33];
    __shared__ float Vs[32][64];
    __shared__ float P[32][33];
    int tid = threadIdx.x;
    int b = blockIdx.x >> 4, hd = blockIdx.x & 15;
    const float* qb = Q + b*HH + hd*HS;
    const float* kb = K + b*HH + hd*HS;
    const float* vb = V + b*HH + hd*HS;
    #pragma unroll
    for (int t = 0; t < 2; t++) {
        int f = tid + t*256;
        int row = f >> 4, c4 = (f & 15) << 2;
        float4 q4 = *(const float4*)(qb + row*RS + c4);
        *(float4*)&Qs[row][c4] = q4;
        float4 k4 = *(const float4*)(kb + row*RS + c4);
        KsT[c4+0][row] = k4.x; KsT[c4+1][row] = k4.y;
        KsT[c4+2][row] = k4.z; KsT[c4+3][row] = k4.w;
        float4 v4 = *(const float4*)(vb + row*RS + c4);
        *(float4*)&Vs[row][c4] = v4;
    }
    __syncthreads();
    #pragma unroll
    for (int t = 0; t < 4; t++) {
        int p = tid + t*256;
        int qr = p >> 5, kr = p & 31;
        float sc = 0.f;
        #pragma unroll
        for (int d = 0; d < 64; d++) sc = fmaf(Qs[qr][d], KsT[d][kr], sc);
        P[qr][kr] = sc * 0.125f;
    }
    __syncthreads();
    int w = tid >> 5, lane = tid & 31;
    #pragma unroll
    for (int r = 0; r < 4; r++) {
        int qr = w + r*8;
        bool vq = qr < L, vk = lane < L;
        float v = (vq && vk) ? P[qr][lane] : -1e30f;
        float mx = v;
        #pragma unroll
        for (int off = 16; off > 0; off >>= 1)
            mx = fmaxf(mx, __shfl_xor_sync(0xFFFFFFFFu, mx, off));
        float e = (vq && vk) ? expf(v - mx) : 0.f;
        float sm = e;
        #pragma unroll
        for (int off = 16; off > 0; off >>= 1)
            sm += __shfl_xor_sync(0xFFFFFFFFu, sm, off);
        P[qr][lane] = vq ? (e / sm) : 0.f;
    }
    __syncthreads();
    __half* ch = ctxh + b*HH + hd*HS;
    #pragma unroll
    for (int t = 0; t < 8; t++) {
        int e = tid + t*256;
        int qr = e >> 6, d = e & 63;
        float acc = 0.f;
        #pragma unroll
        for (int k = 0; k < 32; k++) acc = fmaf(P[qr][k], Vs[k][d], acc);
        ch[qr*RS + d] = __float2half(acc);
    }
}

// ---------------- LayerNorm(x + y), shuffle reductions, fused fp16 convert ----------------
__global__ void ln_kernel(const float* __restrict__ X, const float* __restrict__ Y,
                          const float* __restrict__ gam, const float* __restrict__ bet,
                          float* __restrict__ out,
                          __half* __restrict__ oh, __half* __restrict__ ph)
{
    int row = blockIdx.x;
    int tid = threadIdx.x, wid = tid >> 5, lane = tid & 31;
    const float* x = X + row*HH;
    const float* y = Y + row*HH;
    float v[4];
    float s = 0.f;
    #pragma unroll
    for (int i = 0; i < 4; i++) { v[i] = x[tid + i*256] + y[tid + i*256]; s += v[i]; }
    #pragma unroll
    for (int off = 16; off > 0; off >>= 1) s += __shfl_xor_sync(0xFFFFFFFFu, s, off);
    __shared__ float red[8], red2[8];
    if (lane == 0) red[wid] = s;
    __syncthreads();
    float tot = 0.f;
    #pragma unroll
    for (int wdx = 0; wdx < 8; wdx++) tot += red[wdx];
    float mean = tot * (1.f/1024.f);
    float q = 0.f;
    #pragma unroll
    for (int i = 0; i < 4; i++) { float d = v[i] - mean; q = fmaf(d, d, q); }
    #pragma unroll
    for (int off = 16; off > 0; off >>= 1) q += __shfl_xor_sync(0xFFFFFFFFu, q, off);
    if (lane == 0) red2[wid] = q;
    __syncthreads();
    float tq = 0.f;
    #pragma unroll
    for (int wdx = 0; wdx < 8; wdx++) tq += red2[wdx];
    float inv = rsqrtf(tq * (1.f/1024.f) + 1e-5f);
    #pragma unroll
    for (int i = 0; i < 4; i++) {
        int c = tid + i*256;
        float o = (v[i] - mean) * inv * gam[c] + bet[c];
        out[row*HH + c] = o;
        __half hv = __float2half(o);
        oh[row*HH + c] = hv;
        if (ph) ph[row*HH + c] = hv;
    }
}

// ---------------- r = sigmoid(hf @ Wr), [s][b] layout ----------------
__global__ void r_kernel(const float* __restrict__ h, const float* __restrict__ Wr,
                         float* __restrict__ out_r, int i)
{
    int b = blockIdx.x;
    int tid = threadIdx.x, wid = tid >> 5, lane = tid & 31;
    float acc = 0.f;
    for (int k = tid; k < SQ*HH; k += 256) {
        int s = k >> 10;
        acc = fmaf(h[s*RS + b*HH + (k & 1023)], Wr[k], acc);
    }
    #pragma unroll
    for (int off = 16; off > 0; off >>= 1) acc += __shfl_xor_sync(0xFFFFFFFFu, acc, off);
    __shared__ float red[8];
    if (lane == 0) red[wid] = acc;
    __syncthreads();
    if (tid == 0) {
        float t = 0.f;
        #pragma unroll
        for (int wdx = 0; wdx < 8; wdx++) t += red[wdx];
        out_r[b*TACT + i] = 1.f / (1.f + expf(-t));
    }
}

// ---------------- s_new partials: split-K 32 (one s-position per y-block) ----------------
__global__ void snew_kernel(const float* __restrict__ h, const float* __restrict__ Wso,
                            float* __restrict__ spart)
{
    __shared__ float As[32][36];
    __shared__ float Bs[32][64];
    int tid = threadIdx.x;
    int n0 = blockIdx.x << 6;
    int k0 = blockIdx.y << 10;
    int sblk = blockIdx.y;
    int col = tid & 63;
    int rg  = tid >> 6;
    int ar = tid >> 3, ac4 = (tid & 7) << 2;
    float acc[8] = {};
    for (int kc = 0; kc < 1024; kc += 32) {
        float4 av = *(const float4*)(h + sblk*RS + ar*HH + kc + ac4);
        As[ar][ac4+0] = av.x; As[ar][ac4+1] = av.y;
        As[ar][ac4+2] = av.z; As[ar][ac4+3] = av.w;
        #pragma unroll
        for (int t = 0; t < 2; t++) {
            int f = tid + t*256;
            int kk = f >> 4, c4 = (f & 15) << 2;
            *(float4*)&Bs[kk][c4] = *(const float4*)(Wso + (size_t)(k0 + kc + kk)*HIN + n0 + c4);
        }
        __syncthreads();
        #pragma unroll 8
        for (int kk = 0; kk < 32; kk++) {
            float bv = Bs[kk][col];
            #pragma unroll
            for (int r8 = 0; r8 < 8; r8++)
                acc[r8] = fmaf(As[rg*8 + r8][kk], bv, acc[r8]);
        }
        __syncthreads();
    }
    #pragma unroll
    for (int r8 = 0; r8 < 8; r8++)
        spart[blockIdx.y*(NB*HIN) + (rg*8 + r8)*HIN + n0 + col] = acc[r8];
}

__global__ void fin_kernel(const float* __restrict__ spart, __half* __restrict__ sreluh,
                           float* __restrict__ out_s, int i)
{
    int idx = blockIdx.x*256 + threadIdx.x;   // 16384
    float v = 0.f;
    #pragma unroll
    for (int p = 0; p < 32; p++) v += spart[p*(NB*HIN) + idx];
    v = fmaxf(v, 0.f);
    sreluh[idx] = __float2half(v);
    int b = idx >> 9, n = idx & 511;
    out_s[(b*TACT + i)*HIN + n] = v;
}

// ---------------- host orchestration ----------------
extern "C" void kernel_launch(void* const* d_in, const int* in_sizes, int n_in,
                              void* d_out, int out_size)
{
    const float* history_s = (const float*)d_in[0];
    const float* history_a = (const float*)d_in[1];
    const float* s_in      = (const float*)d_in[2];
    const float* a_list    = (const float*)d_in[3];
    const float* Ws        = (const float*)d_in[4];
    const float* Wa        = (const float*)d_in[5];
    const float* Wq        = (const float*)d_in[6];
    const float* Wk        = (const float*)d_in[7];
    const float* Wv        = (const float*)d_in[8];
    const float* Wo        = (const float*)d_in[9];
    const float* Wfc       = (const float*)d_in[10];
    const float* ln1_g     = (const float*)d_in[11];
    const float* ln1_b     = (const float*)d_in[12];
    const float* ln2_g     = (const float*)d_in[13];
    const float* ln2_b     = (const float*)d_in[14];
    const float* Wr        = (const float*)d_in[15];
    const float* Wso       = (const float*)d_in[16];

    float* out_r = (float*)d_out;             // [B, TA]
    float* out_s = out_r + NB*TACT;           // [B, TA, HIN]

    void* p;
    cudaGetSymbolAddress(&p, g_pe);     float* pe     = (float*)p;
    cudaGetSymbolAddress(&p, g_tokens); float* tokens = (float*)p;
    cudaGetSymbolAddress(&p, g_h);      float* h      = (float*)p;
    cudaGetSymbolAddress(&p, g_qbuf);   float* qbuf   = (float*)p;
    cudaGetSymbolAddress(&p, g_kbig);   float* kbig   = (float*)p;
    cudaGetSymbolAddress(&p, g_vbuf);   float* vb     = (float*)p;
    cudaGetSymbolAddress(&p, g_tmp);    float* tmp    = (float*)p;
    cudaGetSymbolAddress(&p, g_spart);  float* spart  = (float*)p;
    cudaGetSymbolAddress(&p, g_sreluh); __half* sreluh = (__half*)p;
    cudaGetSymbolAddress(&p, g_hh);     __half* hh   = (__half*)p;
    cudaGetSymbolAddress(&p, g_ctxh);   __half* ctxh = (__half*)p;
    cudaGetSymbolAddress(&p, g_phh);    __half* phh  = (__half*)p;
    cudaGetSymbolAddress(&p, g_WhT);    __half* WhT  = (__half*)p;
    cudaGetSymbolAddress(&p, g_WsTh);   __half* WsTh = (__half*)p;

    cudaFuncSetAttribute(gemm_tc,   cudaFuncAttributeMaxDynamicSharedMemorySize, GEMM_SMEM);
    cudaFuncSetAttribute(gemm_qkv3, cudaFuncAttributeMaxDynamicSharedMemorySize, GEMM_SMEM);
    cudaFuncSetAttribute(gemm_qk,   cudaFuncAttributeMaxDynamicSharedMemorySize, GEMM_SMEM);
    cudaFuncSetAttribute(gemm_tok,  cudaFuncAttributeMaxDynamicSharedMemorySize, GEMM_SMEM);

    // side stream + events (fork-join; captured into the graph)
    cudaStream_t s2;
    cudaStreamCreate(&s2);
    cudaEvent_t evLn2[NLAY], evQK[NLAY], evR, evT, evFork;
    for (int j = 0; j < NLAY; j++) {
        cudaEventCreateWithFlags(&evLn2[j], cudaEventDisableTiming);
        cudaEventCreateWithFlags(&evQK[j],  cudaEventDisableTiming);
    }
    cudaEventCreateWithFlags(&evR, cudaEventDisableTiming);
    cudaEventCreateWithFlags(&evT, cudaEventDisableTiming);
    cudaEventCreateWithFlags(&evFork, cudaEventDisableTiming);

    // fork: first op on main records an event; s2 joins the capture by waiting on it.
    pe_kernel<<<SQ, 256>>>(pe);
    cudaEventRecord(evFork, 0);
    cudaStreamWaitEvent(s2, evFork, 0);

    // main: weight conversions.  side: token embeds (independent of W conv).
    wconv_kernel<<<dim3(32, 32, 20), 256>>>(Wq, Wk, Wv, Wo, Wfc, WhT);
    wsconv_kernel<<<dim3(16, 32), 256>>>(Ws, WsTh);

    zero4_kernel<<<TOK_ELEMS/1024, 256, 0, s2>>>(tokens);
    vecmat_relu<<<dim3(NB*THIST, 4), 256, 0, s2>>>(history_s, HIN, Ws, HIN, 1, 0, tokens);
    vecmat_relu<<<dim3(NB*THIST, 4), 256, 0, s2>>>(history_a, AIN, Wa, AIN, 2, 0, tokens);
    vecmat_relu<<<dim3(NB, 4), 256, 0, s2>>>(s_in, HIN, Ws, HIN, 3, 16, tokens);
    vecmat_relu<<<dim3(NB*TACT, 4), 256, 0, s2>>>(a_list, AIN, Wa, AIN, 4, 0, tokens);
    cudaEventRecord(evT, s2);

    for (int i = 0; i < TACT; i++) {
        int posA = 2*THIST + 1 + 2*i;
        int L = posA + 1;
        int M = NB * L;                 // valid rows (prefix), divisible by 64
        int Mt = M >> 6;                // 64-row M-tiles this step
        if (i == 0) cudaStreamWaitEvent(0, evT, 0);   // token embeds ready
        if (i > 0)  cudaStreamWaitEvent(0, evR, 0);   // r of prev step reads h
        addpe_kernel<<<TOK_ELEMS/256, 256>>>(tokens, pe, h, hh, L);

        for (int j = 0; j < NLAY; j++) {
            float* qbj = qbuf + (size_t)j*TOK_ELEMS;
            float* kbj = kbig + (size_t)j*TOK_ELEMS;
            size_t sq = (size_t)(0*4 + j)*WMAT, sk = (size_t)(1*4 + j)*WMAT;
            size_t sv = (size_t)(2*4 + j)*WMAT, so = (size_t)(3*4 + j)*WMAT;
            size_t sf = (size_t)(4*4 + j)*WMAT;

            if (i == 0) {
                gemm_qkv3<<<dim3(8, Mt, 3), 256, GEMM_SMEM>>>(hh, WhT,
                                                              sq, sk, sv, qbj, kbj, vb, M);
            } else {
                gemm_tc<<<dim3(8, Mt), 256, GEMM_SMEM>>>(hh, WhT + sv, vb, M);
                cudaStreamWaitEvent(0, evQK[j], 0);     // Q/K precomputed last step
            }
            attn_kernel<<<NB*NHEAD, 256>>>(L, qbj, kbj, vb, ctxh);
            gemm_tc<<<dim3(8, Mt), 256, GEMM_SMEM>>>(ctxh, WhT + so, tmp, M);
            ln_kernel<<<M, 256>>>(h, tmp, ln1_g + j*HH, ln1_b + j*HH, h, hh, (__half*)0);
            gemm_tc<<<dim3(8, Mt), 256, GEMM_SMEM>>>(hh, WhT + sf, tmp, M);
            ln_kernel<<<M, 256>>>(h, tmp, ln2_g + j*HH, ln2_b + j*HH, h, hh,
                                  phh + (size_t)j*TOK_ELEMS);
            cudaEventRecord(evLn2[j], 0);

            if (i + 1 < TACT) {
                // look-ahead Q/K for next step on the side stream (M+64 rows; pad zero-filled)
                cudaStreamWaitEvent(s2, evLn2[j], 0);
                gemm_qk<<<dim3(8, Mt + 1, 2), 256, GEMM_SMEM, s2>>>(
                    phh + (size_t)j*TOK_ELEMS, WhT, sq, sk, qbj, kbj, M);
                cudaEventRecord(evQK[j], s2);
            }
        }
        // r on the side stream (off critical path); snew/fin on main
        if (i + 1 >= TACT) cudaStreamWaitEvent(s2, evLn2[NLAY-1], 0);
        r_kernel<<<NB, 256, 0, s2>>>(h, Wr, out_r, i);
        cudaEventRecord(evR, s2);
        snew_kernel<<<dim3(8, 32), 256>>>(h, Wso, spart);
        fin_kernel<<<64, 256>>>(spart, sreluh, out_s, i);
        if (i + 1 < TACT)
            gemm_tok<<<dim3(8, 1), 256, GEMM_SMEM>>>(sreluh, WsTh,
                                                     tokens + (size_t)(posA + 1)*NB*HH);
    }
    cudaStreamWaitEvent(0, evR, 0);   // join side stream before returning

    for (int j = 0; j < NLAY; j++) {
        cudaEventDestroy(evLn2[j]);
        cudaEventDestroy(evQK[j]);
    }
    cudaEventDestroy(evR);
    cudaEventDestroy(evT);
    cudaEventDestroy(evFork);
    cudaStreamDestroy(s2);
}

// round 17
// speedup vs baseline: 1.9350x; 1.0834x over previous
#include <cuda_runtime.h>
#include <cuda_fp16.h>
#include <cstdint>
#include <math.h>

#define NB    32
#define SQ    32
#define HH    1024
#define NHEAD 16
#define HS    64
#define NLAY  4
#define THIST 8
#define TACT  8
#define HIN   512
#define AIN   64
#define RS    (NB*HH)          // 32768: row stride between s-positions

#define TOK_ELEMS (NB*SQ*HH)   // 1048576
#define WMAT      (HH*HH)      // 1048576
#define PSZ       (NB*NHEAD*SQ*SQ)   // 524288 floats per layer

// token row layout: row = s*NB + b  (valid rows are prefix [0, 32*L))

// ---------------- scratch (device globals; no allocation) ----------------
__device__ float g_pe[SQ*HH];
__device__ float g_tokens[TOK_ELEMS];
__device__ float g_h[TOK_ELEMS];
__device__ float g_qbuf[NLAY*TOK_ELEMS];   // per-layer Q
__device__ float g_kbig[NLAY*TOK_ELEMS];   // per-layer K
__device__ float g_vbuf[TOK_ELEMS];
__device__ float g_tmp[TOK_ELEMS];
__device__ float g_spart[32*NB*HIN];
__device__ float g_pbuf[NLAY*PSZ];         // softmax probs per layer
__device__ __half g_sreluh[NB*HIN];
__device__ __half g_hh[TOK_ELEMS];                 // fp16 activations
__device__ __half g_ctxh[TOK_ELEMS];
__device__ __half g_phh[NLAY*TOK_ELEMS];
__device__ __half g_WhT[20*WMAT];                  // fp16 weights [N,K]
__device__ __half g_WsTh[HH*HIN];                  // Ws^T fp16 [1024,512]

// ---------------- helpers ----------------
__device__ __forceinline__ uint32_t s2u(const void* p) {
    uint32_t a;
    asm("{ .reg .u64 t; cvta.to.shared.u64 t, %1; cvt.u32.u64 %0, t; }" : "=r"(a) : "l"(p));
    return a;
}

#define LDM4(r, addr) \
    asm volatile("ldmatrix.sync.aligned.m8n8.x4.shared.b16 {%0,%1,%2,%3}, [%4];" \
        : "=r"((r)[0]), "=r"((r)[1]), "=r"((r)[2]), "=r"((r)[3]) : "r"(addr))

#define MMA_F16(d, a, b0v, b1v) \
    asm volatile("mma.sync.aligned.m16n8k16.row.col.f32.f16.f16.f32 " \
        "{%0,%1,%2,%3}, {%4,%5,%6,%7}, {%8,%9}, {%0,%1,%2,%3};" \
        : "+f"((d)[0]), "+f"((d)[1]), "+f"((d)[2]), "+f"((d)[3]) \
        : "r"((a)[0]), "r"((a)[1]), "r"((a)[2]), "r"((a)[3]), "r"(b0v), "r"(b1v))

#define CP_ASYNC16(sa, gp) \
    asm volatile("cp.async.cg.shared.global [%0], [%1], 16;" :: "r"(sa), "l"(gp))
#define CP_ASYNC16Z(sa, gp, sz) \
    asm volatile("cp.async.cg.shared.global [%0], [%1], 16, %2;" :: "r"(sa), "l"(gp), "r"(sz))
#define CP_COMMIT()  asm volatile("cp.async.commit_group;" ::: "memory")
#define CP_WAIT0()   asm volatile("cp.async.wait_group 0;" ::: "memory")
#define CP_WAIT1()   asm volatile("cp.async.wait_group 1;" ::: "memory")
#define CP_WAIT2()   asm volatile("cp.async.wait_group 2;" ::: "memory")

// ---------------- weight transpose + fp16: W[K,N] -> WT[N,K] ----------------
__global__ void wconv_kernel(const float* __restrict__ Wq, const float* __restrict__ Wk,
                             const float* __restrict__ Wv, const float* __restrict__ Wo,
                             const float* __restrict__ Wfc,
                             __half* __restrict__ WhT)
{
    int z = blockIdx.z;                 // 0..19 = type*4 + layer
    int type = z >> 2, layer = z & 3;
    const float* bases[5] = {Wq, Wk, Wv, Wo, Wfc};
    const float* W = bases[type] + (size_t)layer * WMAT;
    __shared__ float t[32][33];
    int x0 = blockIdx.x * 32;  // K
    int y0 = blockIdx.y * 32;  // N
    int tr = threadIdx.x >> 5, tc = threadIdx.x & 31;
    #pragma unroll
    for (int u = 0; u < 4; u++) {
        int r = tr + u * 8;
        t[r][tc] = W[(size_t)(x0 + r) * HH + y0 + tc];
    }
    __syncthreads();
    size_t ob = (size_t)z * WMAT;
    #pragma unroll
    for (int u = 0; u < 4; u++) {
        int r = tr + u * 8;
        WhT[ob + (size_t)(y0 + r) * HH + x0 + tc] = __float2half(t[tc][r]);
    }
}

// Ws [HIN=512, HH=1024] -> WsT [HH, HIN] fp16
__global__ void wsconv_kernel(const float* __restrict__ Ws, __half* __restrict__ WsTh)
{
    __shared__ float t[32][33];
    int x0 = blockIdx.x * 32;  // K (HIN)
    int y0 = blockIdx.y * 32;  // N (HH)
    int tr = threadIdx.x >> 5, tc = threadIdx.x & 31;
    #pragma unroll
    for (int u = 0; u < 4; u++) {
        int r = tr + u * 8;
        t[r][tc] = Ws[(size_t)(x0 + r) * HH + y0 + tc];
    }
    __syncthreads();
    #pragma unroll
    for (int u = 0; u < 4; u++) {
        int r = tr + u * 8;
        WsTh[(size_t)(y0 + r) * HIN + x0 + tc] = __float2half(t[tc][r]);
    }
}

// ---------------- fp16 tensor-core GEMM (mma.sync), 1-term ----------------
// C = A x B^T, A fp16 [M, K], B [N, K] (row stride ldab).
// CTA tile 64(M) x 128(N), K-chunk 64, NST K-stages, 4-buffer pipeline, 2 CTAs/SM.
// Stage (24576 B): A[0,8K) B[8K,24K)
#define STAGE 24576
#define NBUF  4
#define GEMM_SMEM (NBUF*STAGE)    // 98304

__device__ __forceinline__ void issue_stage(uint32_t sbase, int buf,
    const __half* __restrict__ A, const __half* __restrict__ B,
    int bm, int bn, int k0, int tid, int mvalid, int ldab)
{
    uint32_t st = sbase + buf * STAGE;
    #pragma unroll
    for (int u = 0; u < 6; u++) {
        int id = tid + u * 256;             // 0..1535
        if (id < 512) {
            int r = id >> 3, c = id & 7;
            const __half* gp = A + (size_t)(bm + r) * ldab + k0 + c * 8;
            uint32_t sa = st + r * 128 + ((c ^ (r & 7)) << 4);
            uint32_t sz = ((bm + r) < mvalid) ? 16u : 0u;
            CP_ASYNC16Z(sa, gp, sz);
        } else {
            int t = id - 512;               // 0..1023
            int r = t >> 3, c = t & 7;
            const __half* gp = B + (size_t)(bn + r) * ldab + k0 + c * 8;
            uint32_t sa = st + 8192 + r * 128 + ((c ^ (r & 7)) << 4);
            CP_ASYNC16(sa, gp);
        }
    }
    CP_COMMIT();
}

template <int NST>
__device__ __forceinline__ void gemm_core(
    const __half* __restrict__ A, const __half* __restrict__ B,
    float* __restrict__ C, int mvalid, int ldab, int ldc, int mstore, int dorelu)
{
    extern __shared__ char smem[];
    uint32_t sbase = s2u(smem);
    int tid = threadIdx.x, wid = tid >> 5, lane = tid & 31;
    int bm = blockIdx.y << 6, bn = blockIdx.x << 7;
    int warpM = (wid >> 2) << 5;
    int warpN = (wid & 3) << 5;

    issue_stage(sbase, 0, A, B, bm, bn, 0,   tid, mvalid, ldab);
    issue_stage(sbase, 1, A, B, bm, bn, 64,  tid, mvalid, ldab);
    issue_stage(sbase, 2, A, B, bm, bn, 128, tid, mvalid, ldab);

    float acc[2][4][4] = {};

    #pragma unroll
    for (int s = 0; s < NST; s++) {
        int rem = NST - 1 - s;
        if (rem >= 2)      { CP_WAIT2(); }
        else if (rem == 1) { CP_WAIT1(); }
        else               { CP_WAIT0(); }
        __syncthreads();
        if (s + 3 < NST)
            issue_stage(sbase, (s + 3) & 3, A, B, bm, bn, (s + 3) << 6, tid, mvalid, ldab);
        uint32_t st = sbase + (s & 3) * STAGE;
        #pragma unroll
        for (int kk = 0; kk < 4; kk++) {
            uint32_t ah[2][4];
            #pragma unroll
            for (int mt = 0; mt < 2; mt++) {
                int r = warpM + mt * 16 + (lane & 15);
                int ch = kk * 2 + (lane >> 4);
                uint32_t ad = st + r * 128 + ((ch ^ (r & 7)) << 4);
                LDM4(ah[mt], ad);
            }
            uint32_t bh[2][4];
            #pragma unroll
            for (int nt = 0; nt < 2; nt++) {
                int r = warpN + nt * 16 + (lane & 7) + ((lane >> 4) << 3);
                int ch = kk * 2 + ((lane >> 3) & 1);
                uint32_t bd = st + 8192 + r * 128 + ((ch ^ (r & 7)) << 4);
                LDM4(bh[nt], bd);
            }
            #pragma unroll
            for (int mt = 0; mt < 2; mt++) {
                #pragma unroll
                for (int j = 0; j < 4; j++) {
                    uint32_t b0 = bh[j >> 1][(j & 1) * 2], b1 = bh[j >> 1][(j & 1) * 2 + 1];
                    MMA_F16(acc[mt][j], ah[mt], b0, b1);
                }
            }
        }
    }

    #pragma unroll
    for (int mt = 0; mt < 2; mt++) {
        int row = bm + warpM + mt * 16 + (lane >> 2);
        #pragma unroll
        for (int j = 0; j < 4; j++) {
            int col = bn + warpN + j * 8 + ((lane & 3) << 1);
            float v0 = acc[mt][j][0], v1 = acc[mt][j][1];
            float v2 = acc[mt][j][2], v3 = acc[mt][j][3];
            if (dorelu) {
                v0 = fmaxf(v0, 0.f); v1 = fmaxf(v1, 0.f);
                v2 = fmaxf(v2, 0.f); v3 = fmaxf(v3, 0.f);
            }
            if (row < mstore)
                *(float2*)&C[(size_t)row * ldc + col] = make_float2(v0, v1);
            if (row + 8 < mstore)
                *(float2*)&C[(size_t)(row + 8) * ldc + col] = make_float2(v2, v3);
        }
    }
}

__global__ void __launch_bounds__(256, 2) gemm_tc(
    const __half* __restrict__ A, const __half* __restrict__ B,
    float* __restrict__ C, int mvalid)
{
    gemm_core<16>(A, B, C, mvalid, HH, HH, 1 << 30, 0);
}

// step-0 QKV: all operands from current hh
__global__ void __launch_bounds__(256, 2) gemm_qkv3(
    const __half* __restrict__ hh, const __half* __restrict__ WhT,
    size_t sq, size_t sk, size_t sv,
    float* __restrict__ Q, float* __restrict__ K, float* __restrict__ V, int mvalid)
{
    int z = blockIdx.z;
    size_t off = (z == 0) ? sq : (z == 1) ? sk : sv;
    float* C = (z == 0) ? Q : (z == 1) ? K : V;
    gemm_core<16>(hh, WhT + off, C, mvalid, HH, HH, 1 << 30, 0);
}

// look-ahead Q,K for next step from prev_h[j]
__global__ void __launch_bounds__(256, 2) gemm_qk(
    const __half* __restrict__ ph, const __half* __restrict__ WhT,
    size_t sq, size_t sk,
    float* __restrict__ Q, float* __restrict__ K, int mvalid)
{
    int z = blockIdx.z;
    size_t off = (z == 0) ? sq : sk;
    float* C = (z == 0) ? Q : K;
    gemm_core<16>(ph, WhT + off, C, mvalid, HH, HH, 1 << 30, 0);
}

// state-token embed: tokens[rowbase+0..31] = relu(sreluh @ WsT^T), K=512
__global__ void __launch_bounds__(256, 2) gemm_tok(
    const __half* __restrict__ sreluh, const __half* __restrict__ WsTh,
    float* __restrict__ Cdst)
{
    gemm_core<8>(sreluh, WsTh, Cdst, NB, HIN, HH, NB, 1);
}

// ---------------- positional encoding ----------------
__global__ void pe_kernel(float* __restrict__ pe)
{
    int s = blockIdx.x;
    for (int h = threadIdx.x; h < HH; h += 256) {
        float e = (float)(2 * (h / 2)) * (1.0f / HH);
        float freq = exp2f(-e * 13.287712379549449f);   // log2(10000)
        float angle = (float)s * freq;
        pe[s*HH + h] = (h & 1) ? cosf(angle) : sinf(angle);
    }
}

__global__ void zero4_kernel(float* __restrict__ p)
{
    int idx = blockIdx.x*256 + threadIdx.x;
    ((float4*)p)[idx] = make_float4(0.f,0.f,0.f,0.f);
}

// ---------------- small row GEMM + relu into tokens ([s][b] layout) ----------------
__global__ void vecmat_relu(const float* __restrict__ X, int xstride,
                            const float* __restrict__ W, int K,
                            int mode, int off, float* __restrict__ tokens)
{
    int r = blockIdx.x;
    __shared__ float xs[512];
    for (int k = threadIdx.x; k < K; k += 256) xs[k] = X[(size_t)r*xstride + k];
    __syncthreads();
    int drow;
    if      (mode == 1) drow = (2*(r&7))*NB + (r>>3);
    else if (mode == 2) drow = (2*(r&7)+1)*NB + (r>>3);
    else if (mode == 4) drow = (2*THIST + 1 + 2*(r % TACT))*NB + (r / TACT);
    else                drow = off*NB + r;
    int c = blockIdx.y*256 + threadIdx.x;
    float acc = 0.f;
    for (int k = 0; k < K; k++) acc = fmaf(xs[k], W[k*HH + c], acc);
    tokens[drow*HH + c] = fmaxf(acc, 0.f);
}

// ---------------- h = tokens + pe (valid rows; pad rows forced to 0) ----------------
__global__ void addpe_kernel(const float* __restrict__ tokens,
                             const float* __restrict__ pe,
                             float* __restrict__ h,
                             __half* __restrict__ hh, int L)
{
    int i = blockIdx.x*256 + threadIdx.x;
    int srow = i >> 15;                       // s index ([s][b] layout)
    float v = 0.f;
    if (srow < L) v = tokens[i] + pe[srow*HH + (i & 1023)];
    h[i] = v;
    hh[i] = __float2half(v);
}

// ---------------- attention: combined (step 0 only) ----------------
__global__ void attn_kernel(int L, const float* __restrict__ Q,
                            const float* __restrict__ K,
                            const float* __restrict__ V,
                            __half* __restrict__ ctxh)
{
    __shared__ float Qs[32][64];
    __shared__ float KsT[64][33];
    __shared__ float Vs[32][64];
    __shared__ float P[32][33];
    int tid = threadIdx.x;
    int b = blockIdx.x >> 4, hd = blockIdx.x & 15;
    const float* qb = Q + b*HH + hd*HS;
    const float* kb = K + b*HH + hd*HS;
    const float* vb = V + b*HH + hd*HS;
    #pragma unroll
    for (int t = 0; t < 2; t++) {
        int f = tid + t*256;
        int row = f >> 4, c4 = (f & 15) << 2;
        float4 q4 = *(const float4*)(qb + row*RS + c4);
        *(float4*)&Qs[row][c4] = q4;
        float4 k4 = *(const float4*)(kb + row*RS + c4);
        KsT[c4+0][row] = k4.x; KsT[c4+1][row] = k4.y;
        KsT[c4+2][row] = k4.z; KsT[c4+3][row] = k4.w;
        float4 v4 = *(const float4*)(vb + row*RS + c4);
        *(float4*)&Vs[row][c4] = v4;
    }
    __syncthreads();
    #pragma unroll
    for (int t = 0; t < 4; t++) {
        int p = tid + t*256;
        int qr = p >> 5, kr = p & 31;
        float sc = 0.f;
        #pragma unroll
        for (int d = 0; d < 64; d++) sc = fmaf(Qs[qr][d], KsT[d][kr], sc);
        P[qr][kr] = sc * 0.125f;
    }
    __syncthreads();
    int w = tid >> 5, lane = tid & 31;
    #pragma unroll
    for (int r = 0; r < 4; r++) {
        int qr = w + r*8;
        bool vq = qr < L, vk = lane < L;
        float v = (vq && vk) ? P[qr][lane] : -1e30f;
        float mx = v;
        #pragma unroll
        for (int off = 16; off > 0; off >>= 1)
            mx = fmaxf(mx, __shfl_xor_sync(0xFFFFFFFFu, mx, off));
        float e = (vq && vk) ? expf(v - mx) : 0.f;
        float sm = e;
        #pragma unroll
        for (int off = 16; off > 0; off >>= 1)
            sm += __shfl_xor_sync(0xFFFFFFFFu, sm, off);
        P[qr][lane] = vq ? (e / sm) : 0.f;
    }
    __syncthreads();
    __half* ch = ctxh + b*HH + hd*HS;
    #pragma unroll
    for (int t = 0; t < 8; t++) {
        int e = tid + t*256;
        int qr = e >> 6, d = e & 63;
        float acc = 0.f;
        #pragma unroll
        for (int k = 0; k < 32; k++) acc = fmaf(P[qr][k], Vs[k][d], acc);
        ch[qr*RS + d] = __float2half(acc);
    }
}

// ---------------- attention split: scores + softmax (side stream) ----------------
__global__ void attn_sm_kernel(int L, const float* __restrict__ Q,
                               const float* __restrict__ K,
                               float* __restrict__ Pg)
{
    __shared__ float Qs[32][64];
    __shared__ float KsT[64][33];
    __shared__ float P[32][33];
    int tid = threadIdx.x;
    int b = blockIdx.x >> 4, hd = blockIdx.x & 15;
    const float* qb = Q + b*HH + hd*HS;
    const float* kb = K + b*HH + hd*HS;
    #pragma unroll
    for (int t = 0; t < 2; t++) {
        int f = tid + t*256;
        int row = f >> 4, c4 = (f & 15) << 2;
        float4 q4 = *(const float4*)(qb + row*RS + c4);
        *(float4*)&Qs[row][c4] = q4;
        float4 k4 = *(const float4*)(kb + row*RS + c4);
        KsT[c4+0][row] = k4.x; KsT[c4+1][row] = k4.y;
        KsT[c4+2][row] = k4.z; KsT[c4+3][row] = k4.w;
    }
    __syncthreads();
    #pragma unroll
    for (int t = 0; t < 4; t++) {
        int p = tid + t*256;
        int qr = p >> 5, kr = p & 31;
        float sc = 0.f;
        #pragma unroll
        for (int d = 0; d < 64; d++) sc = fmaf(Qs[qr][d], KsT[d][kr], sc);
        P[qr][kr] = sc * 0.125f;
    }
    __syncthreads();
    int w = tid >> 5, lane = tid & 31;
    #pragma unroll
    for (int r = 0; r < 4; r++) {
        int qr = w + r*8;
        bool vq = qr < L, vk = lane < L;
        float v = (vq && vk) ? P[qr][lane] : -1e30f;
        float mx = v;
        #pragma unroll
        for (int off = 16; off > 0; off >>= 1)
            mx = fmaxf(mx, __shfl_xor_sync(0xFFFFFFFFu, mx, off));
        float e = (vq && vk) ? expf(v - mx) : 0.f;
        float sm = e;
        #pragma unroll
        for (int off = 16; off > 0; off >>= 1)
            sm += __shfl_xor_sync(0xFFFFFFFFu, sm, off);
        P[qr][lane] = vq ? (e / sm) : 0.f;
    }
    __syncthreads();
    float* pg = Pg + ((size_t)blockIdx.x << 10);
    #pragma unroll
    for (int t = 0; t < 4; t++) {
        int p = tid + t*256;
        pg[p] = P[p >> 5][p & 31];
    }
}

// ---------------- attention split: P @ V (main stream) ----------------
__global__ void attn_pv_kernel(const float* __restrict__ Pg,
                               const float* __restrict__ V,
                               __half* __restrict__ ctxh)
{
    __shared__ float P[32][33];
    __shared__ float Vs[32][64];
    int tid = threadIdx.x;
    int b = blockIdx.x >> 4, hd = blockIdx.x & 15;
    const float* vb = V + b*HH + hd*HS;
    const float* pg = Pg + ((size_t)blockIdx.x << 10);
    #pragma unroll
    for (int t = 0; t < 2; t++) {
        int f = tid + t*256;
        int row = f >> 4, c4 = (f & 15) << 2;
        float4 v4 = *(const float4*)(vb + row*RS + c4);
        *(float4*)&Vs[row][c4] = v4;
    }
    #pragma unroll
    for (int t = 0; t < 4; t++) {
        int p = tid + t*256;
        P[p >> 5][p & 31] = pg[p];
    }
    __syncthreads();
    __half* ch = ctxh + b*HH + hd*HS;
    #pragma unroll
    for (int t = 0; t < 8; t++) {
        int e = tid + t*256;
        int qr = e >> 6, d = e & 63;
        float acc = 0.f;
        #pragma unroll
        for (int k = 0; k < 32; k++) acc = fmaf(P[qr][k], Vs[k][d], acc);
        ch[qr*RS + d] = __float2half(acc);
    }
}

// ---------------- LayerNorm(x + y), shuffle reductions, fused fp16 convert ----------------
__global__ void ln_kernel(const float* __restrict__ X, const float* __restrict__ Y,
                          const float* __restrict__ gam, const float* __restrict__ bet,
                          float* __restrict__ out,
                          __half* __restrict__ oh, __half* __restrict__ ph)
{
    int row = blockIdx.x;
    int tid = threadIdx.x, wid = tid >> 5, lane = tid & 31;
    const float* x = X + row*HH;
    const float* y = Y + row*HH;
    float v[4];
    float s = 0.f;
    #pragma unroll
    for (int i = 0; i < 4; i++) { v[i] = x[tid + i*256] + y[tid + i*256]; s += v[i]; }
    #pragma unroll
    for (int off = 16; off > 0; off >>= 1) s += __shfl_xor_sync(0xFFFFFFFFu, s, off);
    __shared__ float red[8], red2[8];
    if (lane == 0) red[wid] = s;
    __syncthreads();
    float tot = 0.f;
    #pragma unroll
    for (int wdx = 0; wdx < 8; wdx++) tot += red[wdx];
    float mean = tot * (1.f/1024.f);
    float q = 0.f;
    #pragma unroll
    for (int i = 0; i < 4; i++) { float d = v[i] - mean; q = fmaf(d, d, q); }
    #pragma unroll
    for (int off = 16; off > 0; off >>= 1) q += __shfl_xor_sync(0xFFFFFFFFu, q, off);
    if (lane == 0) red2[wid] = q;
    __syncthreads();
    float tq = 0.f;
    #pragma unroll
    for (int wdx = 0; wdx < 8; wdx++) tq += red2[wdx];
    float inv = rsqrtf(tq * (1.f/1024.f) + 1e-5f);
    #pragma unroll
    for (int i = 0; i < 4; i++) {
        int c = tid + i*256;
        float o = (v[i] - mean) * inv * gam[c] + bet[c];
        out[row*HH + c] = o;
        __half hv = __float2half(o);
        oh[row*HH + c] = hv;
        if (ph) ph[row*HH + c] = hv;
    }
}

// ---------------- r = sigmoid(hf @ Wr), [s][b] layout ----------------
__global__ void r_kernel(const float* __restrict__ h, const float* __restrict__ Wr,
                         float* __restrict__ out_r, int i)
{
    int b = blockIdx.x;
    int tid = threadIdx.x, wid = tid >> 5, lane = tid & 31;
    float acc = 0.f;
    for (int k = tid; k < SQ*HH; k += 256) {
        int s = k >> 10;
        acc = fmaf(h[s*RS + b*HH + (k & 1023)], Wr[k], acc);
    }
    #pragma unroll
    for (int off = 16; off > 0; off >>= 1) acc += __shfl_xor_sync(0xFFFFFFFFu, acc, off);
    __shared__ float red[8];
    if (lane == 0) red[wid] = acc;
    __syncthreads();
    if (tid == 0) {
        float t = 0.f;
        #pragma unroll
        for (int wdx = 0; wdx < 8; wdx++) t += red[wdx];
        out_r[b*TACT + i] = 1.f / (1.f + expf(-t));
    }
}

// ---------------- s_new partials: split-K 32 (one s-position per y-block) ----------------
__global__ void snew_kernel(const float* __restrict__ h, const float* __restrict__ Wso,
                            float* __restrict__ spart)
{
    __shared__ float As[32][36];
    __shared__ float Bs[32][64];
    int tid = threadIdx.x;
    int n0 = blockIdx.x << 6;
    int k0 = blockIdx.y << 10;
    int sblk = blockIdx.y;
    int col = tid & 63;
    int rg  = tid >> 6;
    int ar = tid >> 3, ac4 = (tid & 7) << 2;
    float acc[8] = {};
    for (int kc = 0; kc < 1024; kc += 32) {
        float4 av = *(const float4*)(h + sblk*RS + ar*HH + kc + ac4);
        As[ar][ac4+0] = av.x; As[ar][ac4+1] = av.y;
        As[ar][ac4+2] = av.z; As[ar][ac4+3] = av.w;
        #pragma unroll
        for (int t = 0; t < 2; t++) {
            int f = tid + t*256;
            int kk = f >> 4, c4 = (f & 15) << 2;
            *(float4*)&Bs[kk][c4] = *(const float4*)(Wso + (size_t)(k0 + kc + kk)*HIN + n0 + c4);
        }
        __syncthreads();
        #pragma unroll 8
        for (int kk = 0; kk < 32; kk++) {
            float bv = Bs[kk][col];
            #pragma unroll
            for (int r8 = 0; r8 < 8; r8++)
                acc[r8] = fmaf(As[rg*8 + r8][kk], bv, acc[r8]);
        }
        __syncthreads();
    }
    #pragma unroll
    for (int r8 = 0; r8 < 8; r8++)
        spart[blockIdx.y*(NB*HIN) + (rg*8 + r8)*HIN + n0 + col] = acc[r8];
}

__global__ void fin_kernel(const float* __restrict__ spart, __half* __restrict__ sreluh,
                           float* __restrict__ out_s, int i)
{
    int idx = blockIdx.x*256 + threadIdx.x;   // 16384
    float v = 0.f;
    #pragma unroll
    for (int p = 0; p < 32; p++) v += spart[p*(NB*HIN) + idx];
    v = fmaxf(v, 0.f);
    sreluh[idx] = __float2half(v);
    int b = idx >> 9, n = idx & 511;
    out_s[(b*TACT + i)*HIN + n] = v;
}

// ---------------- host orchestration ----------------
extern "C" void kernel_launch(void* const* d_in, const int* in_sizes, int n_in,
                              void* d_out, int out_size)
{
    const float* history_s = (const float*)d_in[0];
    const float* history_a = (const float*)d_in[1];
    const float* s_in      = (const float*)d_in[2];
    const float* a_list    = (const float*)d_in[3];
    const float* Ws        = (const float*)d_in[4];
    const float* Wa        = (const float*)d_in[5];
    const float* Wq        = (const float*)d_in[6];
    const float* Wk        = (const float*)d_in[7];
    const float* Wv        = (const float*)d_in[8];
    const float* Wo        = (const float*)d_in[9];
    const float* Wfc       = (const float*)d_in[10];
    const float* ln1_g     = (const float*)d_in[11];
    const float* ln1_b     = (const float*)d_in[12];
    const float* ln2_g     = (const float*)d_in[13];
    const float* ln2_b     = (const float*)d_in[14];
    const float* Wr        = (const float*)d_in[15];
    const float* Wso       = (const float*)d_in[16];

    float* out_r = (float*)d_out;             // [B, TA]
    float* out_s = out_r + NB*TACT;           // [B, TA, HIN]

    void* p;
    cudaGetSymbolAddress(&p, g_pe);     float* pe     = (float*)p;
    cudaGetSymbolAddress(&p, g_tokens); float* tokens = (float*)p;
    cudaGetSymbolAddress(&p, g_h);      float* h      = (float*)p;
    cudaGetSymbolAddress(&p, g_qbuf);   float* qbuf   = (float*)p;
    cudaGetSymbolAddress(&p, g_kbig);   float* kbig   = (float*)p;
    cudaGetSymbolAddress(&p, g_vbuf);   float* vb     = (float*)p;
    cudaGetSymbolAddress(&p, g_tmp);    float* tmp    = (float*)p;
    cudaGetSymbolAddress(&p, g_spart);  float* spart  = (float*)p;
    cudaGetSymbolAddress(&p, g_pbuf);   float* pbuf   = (float*)p;
    cudaGetSymbolAddress(&p, g_sreluh); __half* sreluh = (__half*)p;
    cudaGetSymbolAddress(&p, g_hh);     __half* hh   = (__half*)p;
    cudaGetSymbolAddress(&p, g_ctxh);   __half* ctxh = (__half*)p;
    cudaGetSymbolAddress(&p, g_phh);    __half* phh  = (__half*)p;
    cudaGetSymbolAddress(&p, g_WhT);    __half* WhT  = (__half*)p;
    cudaGetSymbolAddress(&p, g_WsTh);   __half* WsTh = (__half*)p;

    cudaFuncSetAttribute(gemm_tc,   cudaFuncAttributeMaxDynamicSharedMemorySize, GEMM_SMEM);
    cudaFuncSetAttribute(gemm_qkv3, cudaFuncAttributeMaxDynamicSharedMemorySize, GEMM_SMEM);
    cudaFuncSetAttribute(gemm_qk,   cudaFuncAttributeMaxDynamicSharedMemorySize, GEMM_SMEM);
    cudaFuncSetAttribute(gemm_tok,  cudaFuncAttributeMaxDynamicSharedMemorySize, GEMM_SMEM);

    // side stream + events (fork-join; captured into the graph)
    cudaStream_t s2;
    cudaStreamCreate(&s2);
    cudaEvent_t evLn2[NLAY], evSM[NLAY], evR, evT, evFork;
    for (int j = 0; j < NLAY; j++) {
        cudaEventCreateWithFlags(&evLn2[j], cudaEventDisableTiming);
        cudaEventCreateWithFlags(&evSM[j],  cudaEventDisableTiming);
    }
    cudaEventCreateWithFlags(&evR, cudaEventDisableTiming);
    cudaEventCreateWithFlags(&evT, cudaEventDisableTiming);
    cudaEventCreateWithFlags(&evFork, cudaEventDisableTiming);

    // fork: first op on main records an event; s2 joins the capture by waiting on it.
    pe_kernel<<<SQ, 256>>>(pe);
    cudaEventRecord(evFork, 0);
    cudaStreamWaitEvent(s2, evFork, 0);

    // main: weight conversions.  side: token embeds (independent of W conv).
    wconv_kernel<<<dim3(32, 32, 20), 256>>>(Wq, Wk, Wv, Wo, Wfc, WhT);
    wsconv_kernel<<<dim3(16, 32), 256>>>(Ws, WsTh);

    zero4_kernel<<<TOK_ELEMS/1024, 256, 0, s2>>>(tokens);
    vecmat_relu<<<dim3(NB*THIST, 4), 256, 0, s2>>>(history_s, HIN, Ws, HIN, 1, 0, tokens);
    vecmat_relu<<<dim3(NB*THIST, 4), 256, 0, s2>>>(history_a, AIN, Wa, AIN, 2, 0, tokens);
    vecmat_relu<<<dim3(NB, 4), 256, 0, s2>>>(s_in, HIN, Ws, HIN, 3, 16, tokens);
    vecmat_relu<<<dim3(NB*TACT, 4), 256, 0, s2>>>(a_list, AIN, Wa, AIN, 4, 0, tokens);
    cudaEventRecord(evT, s2);

    for (int i = 0; i < TACT; i++) {
        int posA = 2*THIST + 1 + 2*i;
        int L = posA + 1;
        int M = NB * L;                 // valid rows (prefix), divisible by 64
        int Mt = M >> 6;                // 64-row M-tiles this step
        if (i == 0) cudaStreamWaitEvent(0, evT, 0);   // token embeds ready
        if (i > 0)  cudaStreamWaitEvent(0, evR, 0);   // r of prev step reads h
        addpe_kernel<<<TOK_ELEMS/256, 256>>>(tokens, pe, h, hh, L);

        // i>0: scores+softmax for all layers on the side stream (Q/K from lookahead;
        // s2 in-order after the producing gemm_qk launches of the previous step)
        if (i > 0) {
            for (int j = 0; j < NLAY; j++) {
                attn_sm_kernel<<<NB*NHEAD, 256, 0, s2>>>(
                    L, qbuf + (size_t)j*TOK_ELEMS, kbig + (size_t)j*TOK_ELEMS,
                    pbuf + (size_t)j*PSZ);
                cudaEventRecord(evSM[j], s2);
            }
        }

        for (int j = 0; j < NLAY; j++) {
            float* qbj = qbuf + (size_t)j*TOK_ELEMS;
            float* kbj = kbig + (size_t)j*TOK_ELEMS;
            size_t sq = (size_t)(0*4 + j)*WMAT, sk = (size_t)(1*4 + j)*WMAT;
            size_t sv = (size_t)(2*4 + j)*WMAT, so = (size_t)(3*4 + j)*WMAT;
            size_t sf = (size_t)(4*4 + j)*WMAT;

            if (i == 0) {
                gemm_qkv3<<<dim3(8, Mt, 3), 256, GEMM_SMEM>>>(hh, WhT,
                                                              sq, sk, sv, qbj, kbj, vb, M);
                attn_kernel<<<NB*NHEAD, 256>>>(L, qbj, kbj, vb, ctxh);
            } else {
                gemm_tc<<<dim3(8, Mt), 256, GEMM_SMEM>>>(hh, WhT + sv, vb, M);
                cudaStreamWaitEvent(0, evSM[j], 0);
                attn_pv_kernel<<<NB*NHEAD, 256>>>(pbuf + (size_t)j*PSZ, vb, ctxh);
            }
            gemm_tc<<<dim3(8, Mt), 256, GEMM_SMEM>>>(ctxh, WhT + so, tmp, M);
            ln_kernel<<<M, 256>>>(h, tmp, ln1_g + j*HH, ln1_b + j*HH, h, hh, (__half*)0);
            gemm_tc<<<dim3(8, Mt), 256, GEMM_SMEM>>>(hh, WhT + sf, tmp, M);
            ln_kernel<<<M, 256>>>(h, tmp, ln2_g + j*HH, ln2_b + j*HH, h, hh,
                                  phh + (size_t)j*TOK_ELEMS);
            cudaEventRecord(evLn2[j], 0);

            if (i + 1 < TACT) {
                // look-ahead Q/K for next step on the side stream (M+64 rows; pad zero-filled)
                cudaStreamWaitEvent(s2, evLn2[j], 0);
                gemm_qk<<<dim3(8, Mt + 1, 2), 256, GEMM_SMEM, s2>>>(
                    phh + (size_t)j*TOK_ELEMS, WhT, sq, sk, qbj, kbj, M);
            }
        }
        // r on the side stream (off critical path); snew/fin on main
        cudaStreamWaitEvent(s2, evLn2[NLAY-1], 0);
        r_kernel<<<NB, 256, 0, s2>>>(h, Wr, out_r, i);
        cudaEventRecord(evR, s2);
        snew_kernel<<<dim3(8, 32), 256>>>(h, Wso, spart);
        fin_kernel<<<64, 256>>>(spart, sreluh, out_s, i);
        if (i + 1 < TACT)
            gemm_tok<<<dim3(8, 1), 256, GEMM_SMEM>>>(sreluh, WsTh,
                                                     tokens + (size_t)(posA + 1)*NB*HH);
    }
    cudaStreamWaitEvent(0, evR, 0);   // join side stream before returning

    for (int j = 0; j < NLAY; j++) {
        cudaEventDestroy(evLn2[j]);
        cudaEventDestroy(evSM[j]);
    }
    cudaEventDestroy(evR);
    cudaEventDestroy(evT);
    cudaEventDestroy(evFork);
    cudaStreamDestroy(s2);
}